// round 11
// baseline (speedup 1.0000x reference)
#include <cuda_runtime.h>
#include <cuda_fp16.h>
#include <cstdint>

#define BSZ    4
#define SEQ    2048
#define DMODEL 512
#define DINNER 1024
#define DSTATE 16
#define DTRANK 32
#define NROWS  (BSZ*SEQ)   // 8192 flattened (b,t) rows
#define NCHUNK 32          // time chunks for parallel scan
#define CLEN   64          // steps per chunk

// ---------------- scratch (static device allocations; no cudaMalloc allowed) ----
__device__ float g_xz[(size_t)NROWS * 2 * DINNER];   // in-proj output [8192, 2048]
__device__ float g_u[(size_t)NROWS * DINNER];        // conv+silu activations
__device__ float g_xdbl[(size_t)NROWS * 64];         // [dt(32) | B(16) | C(16)]

// chunked-scan intermediates
__device__ float g_hpart[(size_t)BSZ * NCHUNK * DINNER * DSTATE];
__device__ float g_acum [(size_t)BSZ * NCHUNK * DINNER * DSTATE];
__device__ float g_hin  [(size_t)BSZ * NCHUNK * DINNER * DSTATE];

// fp16 operands: activations hi/lo (exact 2-term), weights hi only
__device__ __half g_xh[(size_t)NROWS * DMODEL];
__device__ __half g_xl[(size_t)NROWS * DMODEL];
__device__ __half g_wih[(size_t)2 * DINNER * DMODEL];
__device__ __half g_yh[(size_t)NROWS * DINNER];
__device__ __half g_yl[(size_t)NROWS * DINNER];
__device__ __half g_woh[(size_t)DMODEL * DINNER];

// ============================ PTX helpers (sm_100 BASE target only) ==========
__device__ __forceinline__ uint32_t smem_u32(const void* p) {
    uint32_t a;
    asm("{ .reg .u64 t; cvta.to.shared.u64 t, %1; cvt.u32.u64 %0, t; }" : "=r"(a) : "l"(p));
    return a;
}
#define CPA16(s, g) \
    asm volatile("cp.async.cg.shared.global [%0], [%1], 16;" :: "r"(s), "l"(g))
#define CPA_COMMIT() asm volatile("cp.async.commit_group;" ::: "memory")
#define CPA_WAIT(n)  asm volatile("cp.async.wait_group %0;" :: "n"(n) : "memory")
#define LDSM4(r0, r1, r2, r3, a) \
    asm volatile("ldmatrix.sync.aligned.m8n8.x4.shared.b16 {%0,%1,%2,%3}, [%4];" \
                 : "=r"(r0), "=r"(r1), "=r"(r2), "=r"(r3) : "r"(a))
// NOT volatile: register-only op, lets ptxas interleave independent MMAs.
#define MMA16816(d, a, b0, b1) \
    asm("mma.sync.aligned.m16n8k16.row.col.f32.f16.f16.f32 " \
        "{%0,%1,%2,%3}, {%4,%5,%6,%7}, {%8,%9}, {%0,%1,%2,%3};" \
        : "+f"((d)[0]), "+f"((d)[1]), "+f"((d)[2]), "+f"((d)[3]) \
        : "r"((a)[0]), "r"((a)[1]), "r"((a)[2]), "r"((a)[3]), \
          "r"(b0), "r"(b1))

// =============================================================================
// 2-term fp16-split GEMM via mma.sync: C[M,N] = (Ah+Al)@Bh^T = A_fp32 @ fp16(B)^T
// CTA 128x128, BK=32, 128 threads (4 warps 2x2, warp tile 64x64), 2-stage
// cp.async, 80B smem row stride. Requires M%128==0, N%128==0, K%32==0.
// =============================================================================
#define MAT_B   10240          // 128 rows * 80 B
#define STAGE_B (3*MAT_B)      // Ah, Al, Bh
#define GEMM_SMEM (2*STAGE_B)  // 61,440 B

__global__ __launch_bounds__(128, 1)
void gemm2t_mma(const __half* __restrict__ Ah, const __half* __restrict__ Al,
                const __half* __restrict__ Bh,
                float* __restrict__ C, int M, int N, int K) {
    extern __shared__ char smem[];
    const uint32_t sb = smem_u32(smem);
    const int tid = threadIdx.x, wid = tid >> 5, lid = tid & 31;
    const int wm = wid >> 1, wn = wid & 1;          // 2 x 2 warp grid, 64x64 tiles
    const int n0 = blockIdx.x * 128, m0 = blockIdx.y * 128;
    const int NC = K >> 5;                          // K / 32 chunks

#define ISSUE_STAGE(c) do {                                                    \
    int _k0 = (c) << 5;                                                        \
    uint32_t _sb = sb + (((c) & 1) ? STAGE_B : 0);                             \
    _Pragma("unroll")                                                          \
    for (int i = 0; i < 12; ++i) {                                             \
        int idx = tid + (i << 7);                                              \
        int mat = idx >> 9;                                                    \
        int rc  = idx & 511;                                                   \
        int r   = rc >> 2, cc = rc & 3;                                        \
        const __half* src = (mat == 0 ? Ah : mat == 1 ? Al : Bh);              \
        int rowbase = (mat < 2) ? m0 : n0;                                     \
        const __half* g = src + (size_t)(rowbase + r) * K + _k0 + cc * 8;      \
        uint32_t s = _sb + mat * MAT_B + r * 80 + cc * 16;                     \
        CPA16(s, g);                                                           \
    }                                                                          \
    CPA_COMMIT();                                                              \
} while (0)

    float acc[4][8][4];
#pragma unroll
    for (int a = 0; a < 4; ++a)
#pragma unroll
        for (int b = 0; b < 8; ++b)
#pragma unroll
            for (int e = 0; e < 4; ++e) acc[a][b][e] = 0.f;

    const int quad = lid >> 3, lr = lid & 7;
    const int rq = (quad & 1) * 8 + lr;             // row-within-16 for ldmatrix lane
    const int kq = (quad >> 1) * 8;                 // k-offset-within-16 for lane

    ISSUE_STAGE(0);

    for (int c = 0; c < NC; ++c) {
        if (c + 1 < NC) {
            ISSUE_STAGE(c + 1);
            CPA_WAIT(1);
        } else {
            CPA_WAIT(0);
        }
        __syncthreads();
        uint32_t cb = sb + ((c & 1) ? STAGE_B : 0);
        uint32_t ab_h = cb, ab_l = cb + MAT_B, bb_h = cb + 2 * MAT_B;
#pragma unroll
        for (int ks = 0; ks < 2; ++ks) {
            uint32_t ah[4][4], al[4][4], bh[4][4];
            int kk = ks * 16 + kq;
#pragma unroll
            for (int mt = 0; mt < 4; ++mt) {
                uint32_t off = (uint32_t)((wm * 64 + mt * 16 + rq) * 80 + kk * 2);
                LDSM4(ah[mt][0], ah[mt][1], ah[mt][2], ah[mt][3], ab_h + off);
                LDSM4(al[mt][0], al[mt][1], al[mt][2], al[mt][3], ab_l + off);
            }
#pragma unroll
            for (int nb = 0; nb < 4; ++nb) {
                uint32_t off = (uint32_t)((wn * 64 + nb * 16 + rq) * 80 + kk * 2);
                LDSM4(bh[nb][0], bh[nb][1], bh[nb][2], bh[nb][3], bb_h + off);
            }
            // term-major: consecutive MMAs hit distinct accumulators
#pragma unroll
            for (int mt = 0; mt < 4; ++mt)
#pragma unroll
                for (int j = 0; j < 8; ++j) {
                    int nb = j >> 1, sel = j & 1;
                    MMA16816(acc[mt][j], ah[mt], bh[nb][sel], bh[nb][sel + 2]);
                }
#pragma unroll
            for (int mt = 0; mt < 4; ++mt)
#pragma unroll
                for (int j = 0; j < 8; ++j) {
                    int nb = j >> 1, sel = j & 1;
                    MMA16816(acc[mt][j], al[mt], bh[nb][sel], bh[nb][sel + 2]);
                }
        }
        __syncthreads();
    }

    // epilogue
    const int gr = lid >> 2, gc = (lid & 3) * 2;
#pragma unroll
    for (int mt = 0; mt < 4; ++mt) {
        int row = m0 + wm * 64 + mt * 16 + gr;
#pragma unroll
        for (int j = 0; j < 8; ++j) {
            int col = n0 + wn * 64 + j * 8 + gc;
            *(float2*)(C + (size_t)row * N + col) =
                make_float2(acc[mt][j][0], acc[mt][j][1]);
            *(float2*)(C + (size_t)(row + 8) * N + col) =
                make_float2(acc[mt][j][2], acc[mt][j][3]);
        }
    }
#undef ISSUE_STAGE
}

// =============================================================================
// fp32 -> (fp16 hi, fp16 lo) split (activations)
// =============================================================================
__global__ void split16_kernel(const float* __restrict__ s, __half* __restrict__ hi,
                               __half* __restrict__ lo, int n4) {
    int i = blockIdx.x * blockDim.x + threadIdx.x;
    if (i >= n4) return;
    float4 v = ((const float4*)s)[i];
    __half hx = __float2half_rn(v.x), hy = __float2half_rn(v.y);
    __half hz = __float2half_rn(v.z), hw = __float2half_rn(v.w);
    __half2* hp = (__half2*)hi;
    __half2* lp = (__half2*)lo;
    hp[2 * i + 0] = __halves2half2(hx, hy);
    hp[2 * i + 1] = __halves2half2(hz, hw);
    lp[2 * i + 0] = __halves2half2(__float2half_rn(v.x - __half2float(hx)),
                                   __float2half_rn(v.y - __half2float(hy)));
    lp[2 * i + 1] = __halves2half2(__float2half_rn(v.z - __half2float(hz)),
                                   __float2half_rn(v.w - __half2float(hw)));
}

// fp32 -> fp16 cast (weights: hi only)
__global__ void cast16_kernel(const float* __restrict__ s, __half* __restrict__ hi,
                              int n4) {
    int i = blockIdx.x * blockDim.x + threadIdx.x;
    if (i >= n4) return;
    float4 v = ((const float4*)s)[i];
    __half2* hp = (__half2*)hi;
    hp[2 * i + 0] = __halves2half2(__float2half_rn(v.x), __float2half_rn(v.y));
    hp[2 * i + 1] = __halves2half2(__float2half_rn(v.z), __float2half_rn(v.w));
}

// =============================================================================
// Depthwise causal conv (width 4) + SiLU — 4 outputs per thread (sliding window)
// Thread handles rows [4*rg, 4*rg+4) of channel d: 7 loads for 4 outputs.
// SEQ % 4 == 0 -> a row-group never straddles a batch boundary.
// =============================================================================
__global__ void conv_silu_kernel(const float* __restrict__ W_conv,
                                 const float* __restrict__ b_conv) {
    int idx = blockIdx.x * blockDim.x + threadIdx.x;
    if (idx >= (NROWS / 4) * DINNER) return;
    int d  = idx & (DINNER - 1);
    int rg = idx >> 10;                 // row-group (4 rows each)
    int row0 = rg << 2;                 // first flattened row
    int t0 = row0 & (SEQ - 1);          // within-batch time of first row
    const float* base = g_xz + (size_t)row0 * (2 * DINNER) + d;
    float4 w = *(const float4*)(W_conv + d * 4);
    float bias = b_conv[d];
    float xv[7];
#pragma unroll
    for (int j = 0; j < 7; ++j) {
        int t = t0 - 3 + j;
        xv[j] = (t >= 0) ? base[(j - 3) * (2 * DINNER)] : 0.f;
    }
    float* up = g_u + (size_t)row0 * DINNER + d;
#pragma unroll
    for (int i = 0; i < 4; ++i) {
        float acc = bias + xv[i] * w.x + xv[i + 1] * w.y + xv[i + 2] * w.z
                  + xv[i + 3] * w.w;
        float sig = 1.f / (1.f + __expf(-acc));
        up[i * DINNER] = acc * sig;
    }
}

// =============================================================================
// x_dbl[8192,64] = u @ W_x^T
// =============================================================================
__global__ __launch_bounds__(256)
void xdbl_kernel(const float* __restrict__ W_x) {
    __shared__ float Us[32][33];
    __shared__ float Ws[64][33];
    int tid = threadIdx.x;
    int m0  = blockIdx.x * 32;
    int col = tid & 63;
    int rg  = tid >> 6;
    float acc[8] = {};
    for (int k0 = 0; k0 < DINNER; k0 += 32) {
        __syncthreads();
#pragma unroll
        for (int i = 0; i < 4; ++i) {
            int idx = tid + i * 256;
            int r = idx >> 5, k = idx & 31;
            Us[r][k] = g_u[(size_t)(m0 + r) * DINNER + k0 + k];
        }
#pragma unroll
        for (int i = 0; i < 8; ++i) {
            int idx = tid + i * 256;
            int n = idx >> 5, k = idx & 31;
            Ws[n][k] = W_x[(size_t)n * DINNER + k0 + k];
        }
        __syncthreads();
#pragma unroll
        for (int k = 0; k < 32; ++k) {
            float w = Ws[col][k];
#pragma unroll
            for (int rr = 0; rr < 8; ++rr)
                acc[rr] += Us[rg * 8 + rr][k] * w;
        }
    }
#pragma unroll
    for (int rr = 0; rr < 8; ++rr)
        g_xdbl[(size_t)(m0 + rg * 8 + rr) * 64 + col] = acc[rr];
}

// ============== chunked parallel scan helpers ================================
struct AState {
    float Av[4];
    bool fast;
};
__device__ __forceinline__ AState load_astate(const float* A_log, int d, int q) {
    AState s;
    s.fast = true;
#pragma unroll
    for (int i = 0; i < 4; ++i) {
        s.Av[i] = -__expf(A_log[(size_t)d * DSTATE + 4 * q + i]);
        float tgt = -(float)(4 * q + i + 1);
        if (fabsf(s.Av[i] - tgt) > 1e-3f) s.fast = false;
    }
    return s;
}
__device__ __forceinline__ void calc_dA(const AState& s, int q, float delta,
                                        float& dA0, float& dA1, float& dA2, float& dA3) {
    if (s.fast) {
        float r  = __expf(-delta);
        float r2 = r * r;
        float r4 = r2 * r2;
        float r8 = r4 * r4;
        float base = 1.f;
        if (q & 1) base = r4;
        if (q & 2) base *= r8;
        dA0 = base * r;
        dA1 = dA0 * r;
        dA2 = dA1 * r;
        dA3 = dA2 * r;
    } else {
        dA0 = __expf(delta * s.Av[0]);
        dA1 = __expf(delta * s.Av[1]);
        dA2 = __expf(delta * s.Av[2]);
        dA3 = __expf(delta * s.Av[3]);
    }
}

// Fused in-block delta: sdelta[tt][ch] = softplus(b_dt[ch] + dt[tt]·W_dt[ch])
// sdt[64][32] (dt tile), sW[32][33] (W_dt slice, padded). Thread (tg=tid>>5,
// ch=tid&31) computes 16 timesteps; sdt reads broadcast, sW conflict-free.
__device__ __forceinline__ void compute_delta_tile(
    float (*sdelta)[32], const float (*sdt)[32], const float (*sW)[33],
    float bias, int tid) {
    int ch = tid & 31, tg = tid >> 5;
#pragma unroll
    for (int j = 0; j < 16; ++j) {
        int tt = tg * 16 + j;
        float s = bias;
#pragma unroll
        for (int k = 0; k < 32; ++k) s += sdt[tt][k] * sW[ch][k];
        sdelta[tt][ch] = (s > 20.f) ? s : log1pf(__expf(s));
    }
}

// =============================================================================
// Scan pass 1: fused delta + per-chunk A-product and partial state (from h=0).
// blockIdx.x = ((b*32 + dg)*NCHUNK + k), 128 threads.
// =============================================================================
__global__ __launch_bounds__(128)
void scan_p1(const float* __restrict__ A_log, const float* __restrict__ W_dt,
             const float* __restrict__ b_dt) {
    __shared__ float sdelta[CLEN][32];
    __shared__ float su[CLEN][32];
    __shared__ float sB[CLEN][16];
    __shared__ float sdt[CLEN][32];
    __shared__ float sW[32][33];
    int tid = threadIdx.x;
    int k  = blockIdx.x & (NCHUNK - 1);
    int dg = (blockIdx.x >> 5) & 31;
    int b  = blockIdx.x >> 10;
    int d0 = dg * 32;
    int c  = tid >> 2, q = tid & 3;
    int d  = d0 + c;
    size_t rowbase = (size_t)b * SEQ + k * CLEN;

#pragma unroll
    for (int i = 0; i < 16; ++i) {
        int idx = tid + i * 128;
        int tt = idx >> 5, cc = idx & 31;
        size_t grow = rowbase + tt;
        su[tt][cc]  = g_u[grow * DINNER + d0 + cc];
        sdt[tt][cc] = g_xdbl[grow * 64 + cc];          // dt = cols [0,32)
    }
#pragma unroll
    for (int i = 0; i < 8; ++i) {
        int idx = tid + i * 128;
        int tt = idx >> 4, nn = idx & 15;
        sB[tt][nn] = g_xdbl[(rowbase + tt) * 64 + 32 + nn];
    }
#pragma unroll
    for (int i = 0; i < 8; ++i) {
        int idx = tid + i * 128;
        int r = idx >> 5, kk = idx & 31;
        sW[r][kk] = W_dt[(size_t)(d0 + r) * DTRANK + kk];
    }
    float bias = b_dt[d0 + (tid & 31)];
    AState as = load_astate(A_log, d, q);
    __syncthreads();
    compute_delta_tile(sdelta, sdt, sW, bias, tid);
    __syncthreads();

    float h0 = 0.f, h1 = 0.f, h2 = 0.f, h3 = 0.f;
    float P0 = 1.f, P1 = 1.f, P2 = 1.f, P3 = 1.f;
    for (int tt = 0; tt < CLEN; ++tt) {
        float delta = sdelta[tt][c];
        float u     = su[tt][c];
        float4 Bv = *(const float4*)&sB[tt][4 * q];
        float dA0, dA1, dA2, dA3;
        calc_dA(as, q, delta, dA0, dA1, dA2, dA3);
        float du = delta * u;
        h0 = dA0 * h0 + du * Bv.x;
        h1 = dA1 * h1 + du * Bv.y;
        h2 = dA2 * h2 + du * Bv.z;
        h3 = dA3 * h3 + du * Bv.w;
        P0 *= dA0; P1 *= dA1; P2 *= dA2; P3 *= dA3;
    }
    size_t o = (((size_t)b * NCHUNK + k) * DINNER + d) * DSTATE + 4 * q;
    *(float4*)&g_hpart[o] = make_float4(h0, h1, h2, h3);
    *(float4*)&g_acum[o]  = make_float4(P0, P1, P2, P3);
}

// =============================================================================
// Scan pass 2: combine chunk summaries -> incoming state per chunk.
// =============================================================================
__global__ __launch_bounds__(256)
void scan_p2() {
    int idx = blockIdx.x * blockDim.x + threadIdx.x;   // b*16384 + d*16 + n
    int b = idx >> 14, dn = idx & 16383;
    float h = 0.f;
#pragma unroll 4
    for (int k = 0; k < NCHUNK; ++k) {
        size_t o = ((size_t)(b * NCHUNK + k) << 14) + dn;
        g_hin[o] = h;
        h = g_acum[o] * h + g_hpart[o];
    }
}

// =============================================================================
// Scan pass 3: fused delta + re-scan from h_in; emit gated fp16 y hi/lo.
// =============================================================================
__global__ __launch_bounds__(128)
void scan_p3(const float* __restrict__ A_log, const float* __restrict__ W_dt,
             const float* __restrict__ b_dt, const float* __restrict__ Dp) {
    __shared__ float sdelta[CLEN][32];
    __shared__ float su[CLEN][32];
    __shared__ float szg[CLEN][32];
    __shared__ float sB[CLEN][16];
    __shared__ float sC[CLEN][16];
    __shared__ float sdt[CLEN][32];
    __shared__ float sW[32][33];
    int tid = threadIdx.x;
    int k  = blockIdx.x & (NCHUNK - 1);
    int dg = (blockIdx.x >> 5) & 31;
    int b  = blockIdx.x >> 10;
    int d0 = dg * 32;
    int c  = tid >> 2, q = tid & 3;
    int d  = d0 + c;
    size_t rowbase = (size_t)b * SEQ + k * CLEN;

#pragma unroll
    for (int i = 0; i < 16; ++i) {
        int idx = tid + i * 128;
        int tt = idx >> 5, cc = idx & 31;
        size_t grow = rowbase + tt;
        su[tt][cc]  = g_u[grow * DINNER + d0 + cc];
        szg[tt][cc] = g_xz[grow * (2 * DINNER) + DINNER + d0 + cc];
        sdt[tt][cc] = g_xdbl[grow * 64 + cc];
    }
#pragma unroll
    for (int i = 0; i < 8; ++i) {
        int idx = tid + i * 128;
        int tt = idx >> 4, nn = idx & 15;
        sB[tt][nn] = g_xdbl[(rowbase + tt) * 64 + 32 + nn];
        sC[tt][nn] = g_xdbl[(rowbase + tt) * 64 + 48 + nn];
    }
#pragma unroll
    for (int i = 0; i < 8; ++i) {
        int idx = tid + i * 128;
        int r = idx >> 5, kk = idx & 31;
        sW[r][kk] = W_dt[(size_t)(d0 + r) * DTRANK + kk];
    }
    float bias = b_dt[d0 + (tid & 31)];
    AState as = load_astate(A_log, d, q);
    float dp = Dp[d];
    size_t o = (((size_t)b * NCHUNK + k) * DINNER + d) * DSTATE + 4 * q;
    float4 hv = *(const float4*)&g_hin[o];
    float h0 = hv.x, h1 = hv.y, h2 = hv.z, h3 = hv.w;
    __syncthreads();
    compute_delta_tile(sdelta, sdt, sW, bias, tid);
    __syncthreads();

    for (int tt = 0; tt < CLEN; ++tt) {
        float delta = sdelta[tt][c];
        float u     = su[tt][c];
        float4 Bv = *(const float4*)&sB[tt][4 * q];
        float4 Cv = *(const float4*)&sC[tt][4 * q];
        float dA0, dA1, dA2, dA3;
        calc_dA(as, q, delta, dA0, dA1, dA2, dA3);
        float du = delta * u;
        h0 = dA0 * h0 + du * Bv.x;
        h1 = dA1 * h1 + du * Bv.y;
        h2 = dA2 * h2 + du * Bv.z;
        h3 = dA3 * h3 + du * Bv.w;
        float y = h0 * Cv.x + h1 * Cv.y + h2 * Cv.z + h3 * Cv.w;
        y += __shfl_xor_sync(0xffffffffu, y, 1);
        y += __shfl_xor_sync(0xffffffffu, y, 2);
        if (q == 0) {
            float z   = szg[tt][c];
            float sig = 1.f / (1.f + __expf(-z));
            float outv = (y + u * dp) * (z * sig);
            size_t oi = (rowbase + tt) * DINNER + d;
            __half hb = __float2half_rn(outv);
            g_yh[oi] = hb;
            g_yl[oi] = __float2half_rn(outv - __half2float(hb));
        }
    }
}

// =============================================================================
extern "C" void kernel_launch(void* const* d_in, const int* in_sizes, int n_in,
                              void* d_out, int out_size) {
    const float* x      = (const float*)d_in[0];
    const float* W_in   = (const float*)d_in[1];
    const float* W_conv = (const float*)d_in[2];
    const float* b_conv = (const float*)d_in[3];
    const float* W_x    = (const float*)d_in[4];
    const float* W_dt   = (const float*)d_in[5];
    const float* b_dt   = (const float*)d_in[6];
    const float* A_log  = (const float*)d_in[7];
    const float* Dp     = (const float*)d_in[8];
    const float* W_out  = (const float*)d_in[9];
    float* out = (float*)d_out;

    float* xz_p;
    __half *xh, *xl, *wih, *yh, *yl, *woh;
    cudaGetSymbolAddress((void**)&xz_p, g_xz);
    cudaGetSymbolAddress((void**)&xh,  g_xh);
    cudaGetSymbolAddress((void**)&xl,  g_xl);
    cudaGetSymbolAddress((void**)&wih, g_wih);
    cudaGetSymbolAddress((void**)&yh,  g_yh);
    cudaGetSymbolAddress((void**)&yl,  g_yl);
    cudaGetSymbolAddress((void**)&woh, g_woh);

    static int smem_set = 0;
    if (!smem_set) {
        cudaFuncSetAttribute(gemm2t_mma, cudaFuncAttributeMaxDynamicSharedMemorySize,
                             GEMM_SMEM);
        smem_set = 1;
    }

    // 0-2) operand prep (gemm1 stays at launch index 3 for ncu; conv at 4)
    split16_kernel<<<(NROWS * DMODEL / 4 + 255) / 256, 256>>>(x, xh, xl,
                                                              NROWS * DMODEL / 4);
    cast16_kernel<<<(2 * DINNER * DMODEL / 4 + 255) / 256, 256>>>(W_in, wih,
                                                                  2 * DINNER * DMODEL / 4);
    cast16_kernel<<<(DMODEL * DINNER / 4 + 255) / 256, 256>>>(W_out, woh,
                                                              DMODEL * DINNER / 4);
    // 3) xz = x @ W_in^T
    gemm2t_mma<<<dim3(2 * DINNER / 128, NROWS / 128), 128, GEMM_SMEM>>>(
        xh, xl, wih, xz_p, NROWS, 2 * DINNER, DMODEL);
    // 4) u = silu(conv(u_pre))  — 4 outputs/thread
    conv_silu_kernel<<<((NROWS / 4) * DINNER) / 256, 256>>>(W_conv, b_conv);
    // 5) x_dbl = u @ W_x^T
    xdbl_kernel<<<NROWS / 32, 256>>>(W_x);
    // 6-8) chunked parallel scan with fused delta
    scan_p1<<<BSZ * 32 * NCHUNK, 128>>>(A_log, W_dt, b_dt);
    scan_p2<<<BSZ * DINNER * DSTATE / 256, 256>>>();
    scan_p3<<<BSZ * 32 * NCHUNK, 128>>>(A_log, W_dt, b_dt, Dp);
    // 9) out = y @ W_out^T
    gemm2t_mma<<<dim3(DMODEL / 128, NROWS / 128), 128, GEMM_SMEM>>>(
        yh, yl, woh, out, NROWS, DMODEL, DINNER);
}

// round 14
// speedup vs baseline: 1.2884x; 1.2884x over previous
#include <cuda_runtime.h>
#include <cuda_fp16.h>
#include <cstdint>

#define BSZ    4
#define SEQ    2048
#define DMODEL 512
#define DINNER 1024
#define DSTATE 16
#define DTRANK 32
#define NROWS  (BSZ*SEQ)   // 8192 flattened (b,t) rows
#define NCHUNK 32          // time chunks for parallel scan
#define CLEN   64          // steps per chunk

// ---------------- scratch (static device allocations; no cudaMalloc allowed) ----
__device__ float g_xz[(size_t)NROWS * 2 * DINNER];   // in-proj output [8192, 2048]
__device__ float g_u[(size_t)NROWS * DINNER];        // conv+silu activations
__device__ float g_xdbl[(size_t)NROWS * 64];         // [dt(32) | B(16) | C(16)]
__device__ float g_delta[(size_t)NROWS * DINNER];    // softplus(dt@W_dt^T + b)

// chunked-scan intermediates
__device__ float g_hpart[(size_t)BSZ * NCHUNK * DINNER * DSTATE];
__device__ float g_acum [(size_t)BSZ * NCHUNK * DINNER * DSTATE];
__device__ float g_hin  [(size_t)BSZ * NCHUNK * DINNER * DSTATE];

// fp16 operands: activations hi/lo (exact 2-term), weights hi only
__device__ __half g_xh[(size_t)NROWS * DMODEL];
__device__ __half g_xl[(size_t)NROWS * DMODEL];
__device__ __half g_wih[(size_t)2 * DINNER * DMODEL];
__device__ __half g_yh[(size_t)NROWS * DINNER];
__device__ __half g_yl[(size_t)NROWS * DINNER];
__device__ __half g_woh[(size_t)DMODEL * DINNER];

// ============================ PTX helpers (sm_100 BASE target only) ==========
__device__ __forceinline__ uint32_t smem_u32(const void* p) {
    uint32_t a;
    asm("{ .reg .u64 t; cvta.to.shared.u64 t, %1; cvt.u32.u64 %0, t; }" : "=r"(a) : "l"(p));
    return a;
}
#define CPA16(s, g) \
    asm volatile("cp.async.cg.shared.global [%0], [%1], 16;" :: "r"(s), "l"(g))
#define CPA_COMMIT() asm volatile("cp.async.commit_group;" ::: "memory")
#define CPA_WAIT(n)  asm volatile("cp.async.wait_group %0;" :: "n"(n) : "memory")
#define LDSM4(r0, r1, r2, r3, a) \
    asm volatile("ldmatrix.sync.aligned.m8n8.x4.shared.b16 {%0,%1,%2,%3}, [%4];" \
                 : "=r"(r0), "=r"(r1), "=r"(r2), "=r"(r3) : "r"(a))
// NOT volatile: register-only op, lets ptxas interleave independent MMAs.
#define MMA16816(d, a, b0, b1) \
    asm("mma.sync.aligned.m16n8k16.row.col.f32.f16.f16.f32 " \
        "{%0,%1,%2,%3}, {%4,%5,%6,%7}, {%8,%9}, {%0,%1,%2,%3};" \
        : "+f"((d)[0]), "+f"((d)[1]), "+f"((d)[2]), "+f"((d)[3]) \
        : "r"((a)[0]), "r"((a)[1]), "r"((a)[2]), "r"((a)[3]), \
          "r"(b0), "r"(b1))

// =============================================================================
// 2-term fp16-split GEMM via mma.sync: C[M,N] = (Ah+Al)@Bh^T = A_fp32 @ fp16(B)^T
// CTA 128x128, BK=32, 128 threads (4 warps 2x2, warp tile 64x64), 2-stage
// cp.async, 80B smem row stride. Requires M%128==0, N%128==0, K%32==0.
// =============================================================================
#define MAT_B   10240          // 128 rows * 80 B
#define STAGE_B (3*MAT_B)      // Ah, Al, Bh
#define GEMM_SMEM (2*STAGE_B)  // 61,440 B

__global__ __launch_bounds__(128, 1)
void gemm2t_mma(const __half* __restrict__ Ah, const __half* __restrict__ Al,
                const __half* __restrict__ Bh,
                float* __restrict__ C, int M, int N, int K) {
    extern __shared__ char smem[];
    const uint32_t sb = smem_u32(smem);
    const int tid = threadIdx.x, wid = tid >> 5, lid = tid & 31;
    const int wm = wid >> 1, wn = wid & 1;          // 2 x 2 warp grid, 64x64 tiles
    const int n0 = blockIdx.x * 128, m0 = blockIdx.y * 128;
    const int NC = K >> 5;                          // K / 32 chunks

#define ISSUE_STAGE(c) do {                                                    \
    int _k0 = (c) << 5;                                                        \
    uint32_t _sb = sb + (((c) & 1) ? STAGE_B : 0);                             \
    _Pragma("unroll")                                                          \
    for (int i = 0; i < 12; ++i) {                                             \
        int idx = tid + (i << 7);                                              \
        int mat = idx >> 9;                                                    \
        int rc  = idx & 511;                                                   \
        int r   = rc >> 2, cc = rc & 3;                                        \
        const __half* src = (mat == 0 ? Ah : mat == 1 ? Al : Bh);              \
        int rowbase = (mat < 2) ? m0 : n0;                                     \
        const __half* g = src + (size_t)(rowbase + r) * K + _k0 + cc * 8;      \
        uint32_t s = _sb + mat * MAT_B + r * 80 + cc * 16;                     \
        CPA16(s, g);                                                           \
    }                                                                          \
    CPA_COMMIT();                                                              \
} while (0)

    float acc[4][8][4];
#pragma unroll
    for (int a = 0; a < 4; ++a)
#pragma unroll
        for (int b = 0; b < 8; ++b)
#pragma unroll
            for (int e = 0; e < 4; ++e) acc[a][b][e] = 0.f;

    const int quad = lid >> 3, lr = lid & 7;
    const int rq = (quad & 1) * 8 + lr;             // row-within-16 for ldmatrix lane
    const int kq = (quad >> 1) * 8;                 // k-offset-within-16 for lane

    ISSUE_STAGE(0);

    for (int c = 0; c < NC; ++c) {
        if (c + 1 < NC) {
            ISSUE_STAGE(c + 1);
            CPA_WAIT(1);
        } else {
            CPA_WAIT(0);
        }
        __syncthreads();
        uint32_t cb = sb + ((c & 1) ? STAGE_B : 0);
        uint32_t ab_h = cb, ab_l = cb + MAT_B, bb_h = cb + 2 * MAT_B;
#pragma unroll
        for (int ks = 0; ks < 2; ++ks) {
            uint32_t ah[4][4], al[4][4], bh[4][4];
            int kk = ks * 16 + kq;
#pragma unroll
            for (int mt = 0; mt < 4; ++mt) {
                uint32_t off = (uint32_t)((wm * 64 + mt * 16 + rq) * 80 + kk * 2);
                LDSM4(ah[mt][0], ah[mt][1], ah[mt][2], ah[mt][3], ab_h + off);
                LDSM4(al[mt][0], al[mt][1], al[mt][2], al[mt][3], ab_l + off);
            }
#pragma unroll
            for (int nb = 0; nb < 4; ++nb) {
                uint32_t off = (uint32_t)((wn * 64 + nb * 16 + rq) * 80 + kk * 2);
                LDSM4(bh[nb][0], bh[nb][1], bh[nb][2], bh[nb][3], bb_h + off);
            }
            // term-major: consecutive MMAs hit distinct accumulators
#pragma unroll
            for (int mt = 0; mt < 4; ++mt)
#pragma unroll
                for (int j = 0; j < 8; ++j) {
                    int nb = j >> 1, sel = j & 1;
                    MMA16816(acc[mt][j], ah[mt], bh[nb][sel], bh[nb][sel + 2]);
                }
#pragma unroll
            for (int mt = 0; mt < 4; ++mt)
#pragma unroll
                for (int j = 0; j < 8; ++j) {
                    int nb = j >> 1, sel = j & 1;
                    MMA16816(acc[mt][j], al[mt], bh[nb][sel], bh[nb][sel + 2]);
                }
        }
        __syncthreads();
    }

    // epilogue
    const int gr = lid >> 2, gc = (lid & 3) * 2;
#pragma unroll
    for (int mt = 0; mt < 4; ++mt) {
        int row = m0 + wm * 64 + mt * 16 + gr;
#pragma unroll
        for (int j = 0; j < 8; ++j) {
            int col = n0 + wn * 64 + j * 8 + gc;
            *(float2*)(C + (size_t)row * N + col) =
                make_float2(acc[mt][j][0], acc[mt][j][1]);
            *(float2*)(C + (size_t)(row + 8) * N + col) =
                make_float2(acc[mt][j][2], acc[mt][j][3]);
        }
    }
#undef ISSUE_STAGE
}

// =============================================================================
// fp32 -> (fp16 hi, fp16 lo) split (activations)
// =============================================================================
__global__ void split16_kernel(const float* __restrict__ s, __half* __restrict__ hi,
                               __half* __restrict__ lo, int n4) {
    int i = blockIdx.x * blockDim.x + threadIdx.x;
    if (i >= n4) return;
    float4 v = ((const float4*)s)[i];
    __half hx = __float2half_rn(v.x), hy = __float2half_rn(v.y);
    __half hz = __float2half_rn(v.z), hw = __float2half_rn(v.w);
    __half2* hp = (__half2*)hi;
    __half2* lp = (__half2*)lo;
    hp[2 * i + 0] = __halves2half2(hx, hy);
    hp[2 * i + 1] = __halves2half2(hz, hw);
    lp[2 * i + 0] = __halves2half2(__float2half_rn(v.x - __half2float(hx)),
                                   __float2half_rn(v.y - __half2float(hy)));
    lp[2 * i + 1] = __halves2half2(__float2half_rn(v.z - __half2float(hz)),
                                   __float2half_rn(v.w - __half2float(hw)));
}

// fp32 -> fp16 cast (weights: hi only)
__global__ void cast16_kernel(const float* __restrict__ s, __half* __restrict__ hi,
                              int n4) {
    int i = blockIdx.x * blockDim.x + threadIdx.x;
    if (i >= n4) return;
    float4 v = ((const float4*)s)[i];
    __half2* hp = (__half2*)hi;
    hp[2 * i + 0] = __halves2half2(__float2half_rn(v.x), __float2half_rn(v.y));
    hp[2 * i + 1] = __halves2half2(__float2half_rn(v.z), __float2half_rn(v.w));
}

// =============================================================================
// Depthwise causal conv (width 4) + SiLU — 4 outputs per thread (sliding window)
// =============================================================================
__global__ void conv_silu_kernel(const float* __restrict__ W_conv,
                                 const float* __restrict__ b_conv) {
    int idx = blockIdx.x * blockDim.x + threadIdx.x;
    if (idx >= (NROWS / 4) * DINNER) return;
    int d  = idx & (DINNER - 1);
    int rg = idx >> 10;                 // row-group (4 rows each)
    int row0 = rg << 2;
    int t0 = row0 & (SEQ - 1);
    const float* base = g_xz + (size_t)row0 * (2 * DINNER) + d;
    float4 w = *(const float4*)(W_conv + d * 4);
    float bias = b_conv[d];
    float xv[7];
#pragma unroll
    for (int j = 0; j < 7; ++j) {
        int t = t0 - 3 + j;
        xv[j] = (t >= 0) ? base[(j - 3) * (2 * DINNER)] : 0.f;
    }
    float* up = g_u + (size_t)row0 * DINNER + d;
#pragma unroll
    for (int i = 0; i < 4; ++i) {
        float acc = bias + xv[i] * w.x + xv[i + 1] * w.y + xv[i + 2] * w.z
                  + xv[i + 3] * w.w;
        float sig = 1.f / (1.f + __expf(-acc));
        up[i * DINNER] = acc * sig;
    }
}

// =============================================================================
// x_dbl[8192,64] = u @ W_x^T
// =============================================================================
__global__ __launch_bounds__(256)
void xdbl_kernel(const float* __restrict__ W_x) {
    __shared__ float Us[32][33];
    __shared__ float Ws[64][33];
    int tid = threadIdx.x;
    int m0  = blockIdx.x * 32;
    int col = tid & 63;
    int rg  = tid >> 6;
    float acc[8] = {};
    for (int k0 = 0; k0 < DINNER; k0 += 32) {
        __syncthreads();
#pragma unroll
        for (int i = 0; i < 4; ++i) {
            int idx = tid + i * 256;
            int r = idx >> 5, k = idx & 31;
            Us[r][k] = g_u[(size_t)(m0 + r) * DINNER + k0 + k];
        }
#pragma unroll
        for (int i = 0; i < 8; ++i) {
            int idx = tid + i * 256;
            int n = idx >> 5, k = idx & 31;
            Ws[n][k] = W_x[(size_t)n * DINNER + k0 + k];
        }
        __syncthreads();
#pragma unroll
        for (int k = 0; k < 32; ++k) {
            float w = Ws[col][k];
#pragma unroll
            for (int rr = 0; rr < 8; ++rr)
                acc[rr] += Us[rg * 8 + rr][k] * w;
        }
    }
#pragma unroll
    for (int rr = 0; rr < 8; ++rr)
        g_xdbl[(size_t)(m0 + rg * 8 + rr) * 64 + col] = acc[rr];
}

// =============================================================================
// delta = softplus(dt @ W_dt^T + b_dt)   (standalone, known-good config)
// =============================================================================
__global__ __launch_bounds__(256)
void delta_kernel(const float* __restrict__ W_dt, const float* __restrict__ b_dt) {
    __shared__ float sdt[32][33];
    __shared__ float sw[256][33];
    int tid = threadIdx.x;
    int m0 = blockIdx.y * 32;
    int n0 = blockIdx.x * 256;
#pragma unroll
    for (int i = 0; i < 4; ++i) {
        int idx = tid + i * 256;
        int r = idx >> 5, k = idx & 31;
        sdt[r][k] = g_xdbl[(size_t)(m0 + r) * 64 + k];
    }
#pragma unroll
    for (int i = 0; i < 32; ++i) {
        int idx = tid + i * 256;
        int n = idx >> 5, k = idx & 31;
        sw[n][k] = W_dt[(size_t)(n0 + n) * DTRANK + k];
    }
    __syncthreads();
    int m  = tid & 63;
    int rg = tid >> 6;
    float acc[8][4];
#pragma unroll
    for (int rr = 0; rr < 8; ++rr)
#pragma unroll
        for (int j = 0; j < 4; ++j) acc[rr][j] = b_dt[n0 + m + 64 * j];
#pragma unroll
    for (int k = 0; k < 32; ++k) {
        float w[4];
#pragma unroll
        for (int j = 0; j < 4; ++j) w[j] = sw[m + 64 * j][k];
#pragma unroll
        for (int rr = 0; rr < 8; ++rr) {
            float dv = sdt[rg * 8 + rr][k];
#pragma unroll
            for (int j = 0; j < 4; ++j) acc[rr][j] += dv * w[j];
        }
    }
#pragma unroll
    for (int rr = 0; rr < 8; ++rr) {
        int row = m0 + rg * 8 + rr;
#pragma unroll
        for (int j = 0; j < 4; ++j) {
            float s  = acc[rr][j];
            float sp = (s > 20.f) ? s : log1pf(__expf(s));
            g_delta[(size_t)row * DINNER + n0 + m + 64 * j] = sp;
        }
    }
}

// ============== thread-per-channel scan: dA helper ===========================
// Fast path: A[d][n] = -(n+1) -> dA[n] = r^(n+1) via depth-3 mul tree.
// Slow path uses the per-thread Av register array (dead in practice).
__device__ __forceinline__ void calc_dA16(bool fast, float delta,
                                          const float* Av, float* dA) {
    if (fast) {
        float r  = __expf(-delta);
        float r2 = r * r, r3 = r2 * r, r4 = r2 * r2;
        dA[0] = r;        dA[1] = r2;       dA[2] = r3;       dA[3] = r4;
        dA[4] = r4 * r;   dA[5] = r4 * r2;  dA[6] = r4 * r3;  dA[7] = r4 * r4;
        float r8 = dA[7];
        dA[8]  = r8 * r;      dA[9]  = r8 * r2;     dA[10] = r8 * r3;
        dA[11] = r8 * r4;     dA[12] = r8 * dA[4];  dA[13] = r8 * dA[5];
        dA[14] = r8 * dA[6];  dA[15] = r8 * r8;
    } else {
#pragma unroll
        for (int n = 0; n < 16; ++n) dA[n] = __expf(delta * Av[n]);
    }
}

// =============================================================================
// Scan pass 1: thread-per-channel (16 states). Grid: BSZ*8*NCHUNK = 1024 blocks,
// 128 threads. blockIdx.x = ((b*8 + dg)*NCHUNK + k). delta/u stream coalesced
// from global in bursts of 8 (MLP); B staged in smem (broadcast reads).
// =============================================================================
__global__ __launch_bounds__(128)
void scan_p1(const float* __restrict__ A_log) {
    __shared__ float sB[CLEN][16];
    int tid = threadIdx.x;
    int k  = blockIdx.x & (NCHUNK - 1);
    int dg = (blockIdx.x >> 5) & 7;
    int b  = blockIdx.x >> 8;
    int d  = dg * 128 + tid;
    size_t rowbase = (size_t)b * SEQ + k * CLEN;

#pragma unroll
    for (int i = 0; i < 8; ++i) {
        int idx = tid + i * 128;
        int tt = idx >> 4, nn = idx & 15;
        sB[tt][nn] = g_xdbl[(rowbase + tt) * 64 + 32 + nn];
    }
    float Av[16];
    bool fast = true;
#pragma unroll
    for (int n = 0; n < 16; ++n) {
        Av[n] = -__expf(A_log[(size_t)d * DSTATE + n]);
        if (fabsf(Av[n] + (float)(n + 1)) > 1e-3f) fast = false;
    }
    __syncthreads();

    float h[16], P[16];
#pragma unroll
    for (int n = 0; n < 16; ++n) { h[n] = 0.f; P[n] = 1.f; }
    const float* dpp = g_delta + rowbase * DINNER + d;
    const float* upp = g_u + rowbase * DINNER + d;

    for (int t0 = 0; t0 < CLEN; t0 += 8) {
        float dl[8], ul[8];
#pragma unroll
        for (int j = 0; j < 8; ++j) {
            dl[j] = dpp[(size_t)(t0 + j) * DINNER];
            ul[j] = upp[(size_t)(t0 + j) * DINNER];
        }
#pragma unroll
        for (int j = 0; j < 8; ++j) {
            int tt = t0 + j;
            float dA[16];
            calc_dA16(fast, dl[j], Av, dA);
            float du = dl[j] * ul[j];
            float4 B0 = *(const float4*)&sB[tt][0];
            float4 B1 = *(const float4*)&sB[tt][4];
            float4 B2 = *(const float4*)&sB[tt][8];
            float4 B3 = *(const float4*)&sB[tt][12];
            h[0]  = dA[0]  * h[0]  + du * B0.x;  h[1]  = dA[1]  * h[1]  + du * B0.y;
            h[2]  = dA[2]  * h[2]  + du * B0.z;  h[3]  = dA[3]  * h[3]  + du * B0.w;
            h[4]  = dA[4]  * h[4]  + du * B1.x;  h[5]  = dA[5]  * h[5]  + du * B1.y;
            h[6]  = dA[6]  * h[6]  + du * B1.z;  h[7]  = dA[7]  * h[7]  + du * B1.w;
            h[8]  = dA[8]  * h[8]  + du * B2.x;  h[9]  = dA[9]  * h[9]  + du * B2.y;
            h[10] = dA[10] * h[10] + du * B2.z;  h[11] = dA[11] * h[11] + du * B2.w;
            h[12] = dA[12] * h[12] + du * B3.x;  h[13] = dA[13] * h[13] + du * B3.y;
            h[14] = dA[14] * h[14] + du * B3.z;  h[15] = dA[15] * h[15] + du * B3.w;
#pragma unroll
            for (int n = 0; n < 16; ++n) P[n] *= dA[n];
        }
    }
    size_t o = (((size_t)b * NCHUNK + k) * DINNER + d) * DSTATE;
#pragma unroll
    for (int g = 0; g < 4; ++g) {
        *(float4*)&g_hpart[o + 4 * g] = make_float4(h[4*g], h[4*g+1], h[4*g+2], h[4*g+3]);
        *(float4*)&g_acum[o + 4 * g]  = make_float4(P[4*g], P[4*g+1], P[4*g+2], P[4*g+3]);
    }
}

// =============================================================================
// Scan pass 2: combine chunk summaries -> incoming state per chunk.
// =============================================================================
__global__ __launch_bounds__(256)
void scan_p2() {
    int idx = blockIdx.x * blockDim.x + threadIdx.x;   // b*16384 + d*16 + n
    int b = idx >> 14, dn = idx & 16383;
    float h = 0.f;
#pragma unroll 4
    for (int k = 0; k < NCHUNK; ++k) {
        size_t o = ((size_t)(b * NCHUNK + k) << 14) + dn;
        g_hin[o] = h;
        h = g_acum[o] * h + g_hpart[o];
    }
}

// =============================================================================
// Scan pass 3: thread-per-channel re-scan from h_in; no shuffles; gated fp16 out.
// =============================================================================
__global__ __launch_bounds__(128)
void scan_p3(const float* __restrict__ A_log, const float* __restrict__ Dp) {
    __shared__ float sB[CLEN][16];
    __shared__ float sC[CLEN][16];
    int tid = threadIdx.x;
    int k  = blockIdx.x & (NCHUNK - 1);
    int dg = (blockIdx.x >> 5) & 7;
    int b  = blockIdx.x >> 8;
    int d  = dg * 128 + tid;
    size_t rowbase = (size_t)b * SEQ + k * CLEN;

#pragma unroll
    for (int i = 0; i < 8; ++i) {
        int idx = tid + i * 128;
        int tt = idx >> 4, nn = idx & 15;
        sB[tt][nn] = g_xdbl[(rowbase + tt) * 64 + 32 + nn];
        sC[tt][nn] = g_xdbl[(rowbase + tt) * 64 + 48 + nn];
    }
    float Av[16];
    bool fast = true;
#pragma unroll
    for (int n = 0; n < 16; ++n) {
        Av[n] = -__expf(A_log[(size_t)d * DSTATE + n]);
        if (fabsf(Av[n] + (float)(n + 1)) > 1e-3f) fast = false;
    }
    float dpv = Dp[d];
    float h[16];
    size_t o = (((size_t)b * NCHUNK + k) * DINNER + d) * DSTATE;
#pragma unroll
    for (int g = 0; g < 4; ++g) {
        float4 hv = *(const float4*)&g_hin[o + 4 * g];
        h[4*g] = hv.x; h[4*g+1] = hv.y; h[4*g+2] = hv.z; h[4*g+3] = hv.w;
    }
    __syncthreads();

    const float* dpp = g_delta + rowbase * DINNER + d;
    const float* upp = g_u + rowbase * DINNER + d;
    const float* zpp = g_xz + rowbase * (2 * DINNER) + DINNER + d;

    for (int t0 = 0; t0 < CLEN; t0 += 8) {
        float dl[8], ul[8], zl[8];
#pragma unroll
        for (int j = 0; j < 8; ++j) {
            dl[j] = dpp[(size_t)(t0 + j) * DINNER];
            ul[j] = upp[(size_t)(t0 + j) * DINNER];
            zl[j] = zpp[(size_t)(t0 + j) * (2 * DINNER)];
        }
#pragma unroll
        for (int j = 0; j < 8; ++j) {
            int tt = t0 + j;
            float dA[16];
            calc_dA16(fast, dl[j], Av, dA);
            float du = dl[j] * ul[j];
            float4 B0 = *(const float4*)&sB[tt][0];
            float4 B1 = *(const float4*)&sB[tt][4];
            float4 B2 = *(const float4*)&sB[tt][8];
            float4 B3 = *(const float4*)&sB[tt][12];
            h[0]  = dA[0]  * h[0]  + du * B0.x;  h[1]  = dA[1]  * h[1]  + du * B0.y;
            h[2]  = dA[2]  * h[2]  + du * B0.z;  h[3]  = dA[3]  * h[3]  + du * B0.w;
            h[4]  = dA[4]  * h[4]  + du * B1.x;  h[5]  = dA[5]  * h[5]  + du * B1.y;
            h[6]  = dA[6]  * h[6]  + du * B1.z;  h[7]  = dA[7]  * h[7]  + du * B1.w;
            h[8]  = dA[8]  * h[8]  + du * B2.x;  h[9]  = dA[9]  * h[9]  + du * B2.y;
            h[10] = dA[10] * h[10] + du * B2.z;  h[11] = dA[11] * h[11] + du * B2.w;
            h[12] = dA[12] * h[12] + du * B3.x;  h[13] = dA[13] * h[13] + du * B3.y;
            h[14] = dA[14] * h[14] + du * B3.z;  h[15] = dA[15] * h[15] + du * B3.w;
            float4 C0 = *(const float4*)&sC[tt][0];
            float4 C1 = *(const float4*)&sC[tt][4];
            float4 C2 = *(const float4*)&sC[tt][8];
            float4 C3 = *(const float4*)&sC[tt][12];
            float y0 = h[0]*C0.x + h[1]*C0.y + h[2]*C0.z + h[3]*C0.w;
            float y1 = h[4]*C1.x + h[5]*C1.y + h[6]*C1.z + h[7]*C1.w;
            float y2 = h[8]*C2.x + h[9]*C2.y + h[10]*C2.z + h[11]*C2.w;
            float y3 = h[12]*C3.x + h[13]*C3.y + h[14]*C3.z + h[15]*C3.w;
            float y = (y0 + y1) + (y2 + y3);
            float z = zl[j];
            float sig = 1.f / (1.f + __expf(-z));
            float outv = (y + ul[j] * dpv) * (z * sig);
            size_t oi = (rowbase + tt) * DINNER + d;
            __half hb = __float2half_rn(outv);
            g_yh[oi] = hb;
            g_yl[oi] = __float2half_rn(outv - __half2float(hb));
        }
    }
}

// =============================================================================
extern "C" void kernel_launch(void* const* d_in, const int* in_sizes, int n_in,
                              void* d_out, int out_size) {
    const float* x      = (const float*)d_in[0];
    const float* W_in   = (const float*)d_in[1];
    const float* W_conv = (const float*)d_in[2];
    const float* b_conv = (const float*)d_in[3];
    const float* W_x    = (const float*)d_in[4];
    const float* W_dt   = (const float*)d_in[5];
    const float* b_dt   = (const float*)d_in[6];
    const float* A_log  = (const float*)d_in[7];
    const float* Dp     = (const float*)d_in[8];
    const float* W_out  = (const float*)d_in[9];
    float* out = (float*)d_out;

    float* xz_p;
    __half *xh, *xl, *wih, *yh, *yl, *woh;
    cudaGetSymbolAddress((void**)&xz_p, g_xz);
    cudaGetSymbolAddress((void**)&xh,  g_xh);
    cudaGetSymbolAddress((void**)&xl,  g_xl);
    cudaGetSymbolAddress((void**)&wih, g_wih);
    cudaGetSymbolAddress((void**)&yh,  g_yh);
    cudaGetSymbolAddress((void**)&yl,  g_yl);
    cudaGetSymbolAddress((void**)&woh, g_woh);

    static int smem_set = 0;
    if (!smem_set) {
        cudaFuncSetAttribute(gemm2t_mma, cudaFuncAttributeMaxDynamicSharedMemorySize,
                             GEMM_SMEM);
        smem_set = 1;
    }

    // 0-2) operand prep (gemm1 stays at launch index 3 for ncu)
    split16_kernel<<<(NROWS * DMODEL / 4 + 255) / 256, 256>>>(x, xh, xl,
                                                              NROWS * DMODEL / 4);
    cast16_kernel<<<(2 * DINNER * DMODEL / 4 + 255) / 256, 256>>>(W_in, wih,
                                                                  2 * DINNER * DMODEL / 4);
    cast16_kernel<<<(DMODEL * DINNER / 4 + 255) / 256, 256>>>(W_out, woh,
                                                              DMODEL * DINNER / 4);
    // 3) xz = x @ W_in^T
    gemm2t_mma<<<dim3(2 * DINNER / 128, NROWS / 128), 128, GEMM_SMEM>>>(
        xh, xl, wih, xz_p, NROWS, 2 * DINNER, DMODEL);
    // 4) u = silu(conv(u_pre))
    conv_silu_kernel<<<((NROWS / 4) * DINNER) / 256, 256>>>(W_conv, b_conv);
    // 5) x_dbl = u @ W_x^T
    xdbl_kernel<<<NROWS / 32, 256>>>(W_x);
    // 6) delta = softplus(dt @ W_dt^T + b_dt)
    delta_kernel<<<dim3(DINNER / 256, NROWS / 32), 256>>>(W_dt, b_dt);
    // 7-9) chunked parallel scan, thread-per-channel
    scan_p1<<<BSZ * 8 * NCHUNK, 128>>>(A_log);
    scan_p2<<<BSZ * DINNER * DSTATE / 256, 256>>>();
    scan_p3<<<BSZ * 8 * NCHUNK, 128>>>(A_log, Dp);
    // 10) out = y @ W_out^T
    gemm2t_mma<<<dim3(DMODEL / 128, NROWS / 128), 128, GEMM_SMEM>>>(
        yh, yl, woh, out, NROWS, DMODEL, DINNER);
}

// round 15
// speedup vs baseline: 1.6241x; 1.2606x over previous
#include <cuda_runtime.h>
#include <cuda_fp16.h>
#include <cstdint>

#define BSZ    4
#define SEQ    2048
#define DMODEL 512
#define DINNER 1024
#define DSTATE 16
#define DTRANK 32
#define NROWS  (BSZ*SEQ)   // 8192 flattened (b,t) rows
#define NCHUNK 32          // time chunks for parallel scan
#define CLEN   64          // steps per chunk

// ---------------- scratch (static device allocations; no cudaMalloc allowed) ----
__device__ float g_xz[(size_t)NROWS * 2 * DINNER];   // in-proj output [8192, 2048]
__device__ float g_u[(size_t)NROWS * DINNER];        // conv+silu activations
__device__ float g_xdbl[(size_t)NROWS * 64];         // [dt(32) | B(16) | C(16)]
__device__ float g_delta[(size_t)NROWS * DINNER];    // softplus(dt@W_dt^T + b)

// chunked-scan intermediates
__device__ float g_hpart[(size_t)BSZ * NCHUNK * DINNER * DSTATE];
__device__ float g_acum [(size_t)BSZ * NCHUNK * DINNER * DSTATE];
__device__ float g_hin  [(size_t)BSZ * NCHUNK * DINNER * DSTATE];

// fp16 operands (1-term: activations and weights both rounded to fp16)
__device__ __half g_xh[(size_t)NROWS * DMODEL];
__device__ __half g_wih[(size_t)2 * DINNER * DMODEL];
__device__ __half g_yh[(size_t)NROWS * DINNER];
__device__ __half g_woh[(size_t)DMODEL * DINNER];

// ============================ PTX helpers (sm_100 BASE target only) ==========
__device__ __forceinline__ uint32_t smem_u32(const void* p) {
    uint32_t a;
    asm("{ .reg .u64 t; cvta.to.shared.u64 t, %1; cvt.u32.u64 %0, t; }" : "=r"(a) : "l"(p));
    return a;
}
#define CPA16(s, g) \
    asm volatile("cp.async.cg.shared.global [%0], [%1], 16;" :: "r"(s), "l"(g))
#define CPA_COMMIT() asm volatile("cp.async.commit_group;" ::: "memory")
#define CPA_WAIT(n)  asm volatile("cp.async.wait_group %0;" :: "n"(n) : "memory")
#define LDSM4(r0, r1, r2, r3, a) \
    asm volatile("ldmatrix.sync.aligned.m8n8.x4.shared.b16 {%0,%1,%2,%3}, [%4];" \
                 : "=r"(r0), "=r"(r1), "=r"(r2), "=r"(r3) : "r"(a))
// NOT volatile: register-only op, lets ptxas interleave independent MMAs.
#define MMA16816(d, a, b0, b1) \
    asm("mma.sync.aligned.m16n8k16.row.col.f32.f16.f16.f32 " \
        "{%0,%1,%2,%3}, {%4,%5,%6,%7}, {%8,%9}, {%0,%1,%2,%3};" \
        : "+f"((d)[0]), "+f"((d)[1]), "+f"((d)[2]), "+f"((d)[3]) \
        : "r"((a)[0]), "r"((a)[1]), "r"((a)[2]), "r"((a)[3]), \
          "r"(b0), "r"(b1))

// =============================================================================
// 1-term fp16 GEMM via mma.sync: C[M,N] = fp16(A) @ fp16(B)^T  (fp32 accum)
// CTA 128x128, BK=32, 128 threads (4 warps 2x2, warp tile 64x64), 2-stage
// cp.async, 80B smem row stride. Requires M%128==0, N%128==0, K%32==0.
// =============================================================================
#define MAT_B   10240          // 128 rows * 80 B
#define STAGE_B (2*MAT_B)      // Ah, Bh
#define GEMM_SMEM (2*STAGE_B)  // 40,960 B

__global__ __launch_bounds__(128, 1)
void gemm1t_mma(const __half* __restrict__ Ah, const __half* __restrict__ Bh,
                float* __restrict__ C, int M, int N, int K) {
    extern __shared__ char smem[];
    const uint32_t sb = smem_u32(smem);
    const int tid = threadIdx.x, wid = tid >> 5, lid = tid & 31;
    const int wm = wid >> 1, wn = wid & 1;          // 2 x 2 warp grid, 64x64 tiles
    const int n0 = blockIdx.x * 128, m0 = blockIdx.y * 128;
    const int NC = K >> 5;                          // K / 32 chunks

#define ISSUE_STAGE(c) do {                                                    \
    int _k0 = (c) << 5;                                                        \
    uint32_t _sb = sb + (((c) & 1) ? STAGE_B : 0);                             \
    _Pragma("unroll")                                                          \
    for (int i = 0; i < 8; ++i) {                                              \
        int idx = tid + (i << 7);                                              \
        int mat = idx >> 9;                                                    \
        int rc  = idx & 511;                                                   \
        int r   = rc >> 2, cc = rc & 3;                                        \
        const __half* src = (mat == 0 ? Ah : Bh);                              \
        int rowbase = (mat == 0) ? m0 : n0;                                    \
        const __half* g = src + (size_t)(rowbase + r) * K + _k0 + cc * 8;      \
        uint32_t s = _sb + mat * MAT_B + r * 80 + cc * 16;                     \
        CPA16(s, g);                                                           \
    }                                                                          \
    CPA_COMMIT();                                                              \
} while (0)

    float acc[4][8][4];
#pragma unroll
    for (int a = 0; a < 4; ++a)
#pragma unroll
        for (int b = 0; b < 8; ++b)
#pragma unroll
            for (int e = 0; e < 4; ++e) acc[a][b][e] = 0.f;

    const int quad = lid >> 3, lr = lid & 7;
    const int rq = (quad & 1) * 8 + lr;             // row-within-16 for ldmatrix lane
    const int kq = (quad >> 1) * 8;                 // k-offset-within-16 for lane

    ISSUE_STAGE(0);

    for (int c = 0; c < NC; ++c) {
        if (c + 1 < NC) {
            ISSUE_STAGE(c + 1);
            CPA_WAIT(1);
        } else {
            CPA_WAIT(0);
        }
        __syncthreads();
        uint32_t cb = sb + ((c & 1) ? STAGE_B : 0);
        uint32_t ab_h = cb, bb_h = cb + MAT_B;
#pragma unroll
        for (int ks = 0; ks < 2; ++ks) {
            uint32_t ah[4][4], bh[4][4];
            int kk = ks * 16 + kq;
#pragma unroll
            for (int mt = 0; mt < 4; ++mt) {
                uint32_t off = (uint32_t)((wm * 64 + mt * 16 + rq) * 80 + kk * 2);
                LDSM4(ah[mt][0], ah[mt][1], ah[mt][2], ah[mt][3], ab_h + off);
            }
#pragma unroll
            for (int nb = 0; nb < 4; ++nb) {
                uint32_t off = (uint32_t)((wn * 64 + nb * 16 + rq) * 80 + kk * 2);
                LDSM4(bh[nb][0], bh[nb][1], bh[nb][2], bh[nb][3], bb_h + off);
            }
#pragma unroll
            for (int mt = 0; mt < 4; ++mt)
#pragma unroll
                for (int j = 0; j < 8; ++j) {
                    int nb = j >> 1, sel = j & 1;
                    MMA16816(acc[mt][j], ah[mt], bh[nb][sel], bh[nb][sel + 2]);
                }
        }
        __syncthreads();
    }

    // epilogue
    const int gr = lid >> 2, gc = (lid & 3) * 2;
#pragma unroll
    for (int mt = 0; mt < 4; ++mt) {
        int row = m0 + wm * 64 + mt * 16 + gr;
#pragma unroll
        for (int j = 0; j < 8; ++j) {
            int col = n0 + wn * 64 + j * 8 + gc;
            *(float2*)(C + (size_t)row * N + col) =
                make_float2(acc[mt][j][0], acc[mt][j][1]);
            *(float2*)(C + (size_t)(row + 8) * N + col) =
                make_float2(acc[mt][j][2], acc[mt][j][3]);
        }
    }
#undef ISSUE_STAGE
}

// fp32 -> fp16 cast
__global__ void cast16_kernel(const float* __restrict__ s, __half* __restrict__ hi,
                              int n4) {
    int i = blockIdx.x * blockDim.x + threadIdx.x;
    if (i >= n4) return;
    float4 v = ((const float4*)s)[i];
    __half2* hp = (__half2*)hi;
    hp[2 * i + 0] = __halves2half2(__float2half_rn(v.x), __float2half_rn(v.y));
    hp[2 * i + 1] = __halves2half2(__float2half_rn(v.z), __float2half_rn(v.w));
}

// =============================================================================
// Depthwise causal conv (width 4) + SiLU — 4 outputs per thread (sliding window)
// =============================================================================
__global__ void conv_silu_kernel(const float* __restrict__ W_conv,
                                 const float* __restrict__ b_conv) {
    int idx = blockIdx.x * blockDim.x + threadIdx.x;
    if (idx >= (NROWS / 4) * DINNER) return;
    int d  = idx & (DINNER - 1);
    int rg = idx >> 10;                 // row-group (4 rows each)
    int row0 = rg << 2;
    int t0 = row0 & (SEQ - 1);
    const float* base = g_xz + (size_t)row0 * (2 * DINNER) + d;
    float4 w = *(const float4*)(W_conv + d * 4);
    float bias = b_conv[d];
    float xv[7];
#pragma unroll
    for (int j = 0; j < 7; ++j) {
        int t = t0 - 3 + j;
        xv[j] = (t >= 0) ? base[(j - 3) * (2 * DINNER)] : 0.f;
    }
    float* up = g_u + (size_t)row0 * DINNER + d;
#pragma unroll
    for (int i = 0; i < 4; ++i) {
        float acc = bias + xv[i] * w.x + xv[i + 1] * w.y + xv[i + 2] * w.z
                  + xv[i + 3] * w.w;
        float sig = 1.f / (1.f + __expf(-acc));
        up[i * DINNER] = acc * sig;
    }
}

// =============================================================================
// x_dbl[8192,64] = u @ W_x^T
// =============================================================================
__global__ __launch_bounds__(256)
void xdbl_kernel(const float* __restrict__ W_x) {
    __shared__ float Us[32][33];
    __shared__ float Ws[64][33];
    int tid = threadIdx.x;
    int m0  = blockIdx.x * 32;
    int col = tid & 63;
    int rg  = tid >> 6;
    float acc[8] = {};
    for (int k0 = 0; k0 < DINNER; k0 += 32) {
        __syncthreads();
#pragma unroll
        for (int i = 0; i < 4; ++i) {
            int idx = tid + i * 256;
            int r = idx >> 5, k = idx & 31;
            Us[r][k] = g_u[(size_t)(m0 + r) * DINNER + k0 + k];
        }
#pragma unroll
        for (int i = 0; i < 8; ++i) {
            int idx = tid + i * 256;
            int n = idx >> 5, k = idx & 31;
            Ws[n][k] = W_x[(size_t)n * DINNER + k0 + k];
        }
        __syncthreads();
#pragma unroll
        for (int k = 0; k < 32; ++k) {
            float w = Ws[col][k];
#pragma unroll
            for (int rr = 0; rr < 8; ++rr)
                acc[rr] += Us[rg * 8 + rr][k] * w;
        }
    }
#pragma unroll
    for (int rr = 0; rr < 8; ++rr)
        g_xdbl[(size_t)(m0 + rg * 8 + rr) * 64 + col] = acc[rr];
}

// =============================================================================
// delta = softplus(dt @ W_dt^T + b_dt)
// =============================================================================
__global__ __launch_bounds__(256)
void delta_kernel(const float* __restrict__ W_dt, const float* __restrict__ b_dt) {
    __shared__ float sdt[32][33];
    __shared__ float sw[256][33];
    int tid = threadIdx.x;
    int m0 = blockIdx.y * 32;
    int n0 = blockIdx.x * 256;
#pragma unroll
    for (int i = 0; i < 4; ++i) {
        int idx = tid + i * 256;
        int r = idx >> 5, k = idx & 31;
        sdt[r][k] = g_xdbl[(size_t)(m0 + r) * 64 + k];
    }
#pragma unroll
    for (int i = 0; i < 32; ++i) {
        int idx = tid + i * 256;
        int n = idx >> 5, k = idx & 31;
        sw[n][k] = W_dt[(size_t)(n0 + n) * DTRANK + k];
    }
    __syncthreads();
    int m  = tid & 63;
    int rg = tid >> 6;
    float acc[8][4];
#pragma unroll
    for (int rr = 0; rr < 8; ++rr)
#pragma unroll
        for (int j = 0; j < 4; ++j) acc[rr][j] = b_dt[n0 + m + 64 * j];
#pragma unroll
    for (int k = 0; k < 32; ++k) {
        float w[4];
#pragma unroll
        for (int j = 0; j < 4; ++j) w[j] = sw[m + 64 * j][k];
#pragma unroll
        for (int rr = 0; rr < 8; ++rr) {
            float dv = sdt[rg * 8 + rr][k];
#pragma unroll
            for (int j = 0; j < 4; ++j) acc[rr][j] += dv * w[j];
        }
    }
#pragma unroll
    for (int rr = 0; rr < 8; ++rr) {
        int row = m0 + rg * 8 + rr;
#pragma unroll
        for (int j = 0; j < 4; ++j) {
            float s  = acc[rr][j];
            float sp = (s > 20.f) ? s : log1pf(__expf(s));
            g_delta[(size_t)row * DINNER + n0 + m + 64 * j] = sp;
        }
    }
}

// ============== thread-per-channel scan: dA helper ===========================
__device__ __forceinline__ void calc_dA16(bool fast, float delta,
                                          const float* Av, float* dA) {
    if (fast) {
        float r  = __expf(-delta);
        float r2 = r * r, r3 = r2 * r, r4 = r2 * r2;
        dA[0] = r;        dA[1] = r2;       dA[2] = r3;       dA[3] = r4;
        dA[4] = r4 * r;   dA[5] = r4 * r2;  dA[6] = r4 * r3;  dA[7] = r4 * r4;
        float r8 = dA[7];
        dA[8]  = r8 * r;      dA[9]  = r8 * r2;     dA[10] = r8 * r3;
        dA[11] = r8 * r4;     dA[12] = r8 * dA[4];  dA[13] = r8 * dA[5];
        dA[14] = r8 * dA[6];  dA[15] = r8 * r8;
    } else {
#pragma unroll
        for (int n = 0; n < 16; ++n) dA[n] = __expf(delta * Av[n]);
    }
}

// =============================================================================
// Scan pass 1: thread-per-channel (16 states).
// =============================================================================
__global__ __launch_bounds__(128)
void scan_p1(const float* __restrict__ A_log) {
    __shared__ float sB[CLEN][16];
    int tid = threadIdx.x;
    int k  = blockIdx.x & (NCHUNK - 1);
    int dg = (blockIdx.x >> 5) & 7;
    int b  = blockIdx.x >> 8;
    int d  = dg * 128 + tid;
    size_t rowbase = (size_t)b * SEQ + k * CLEN;

#pragma unroll
    for (int i = 0; i < 8; ++i) {
        int idx = tid + i * 128;
        int tt = idx >> 4, nn = idx & 15;
        sB[tt][nn] = g_xdbl[(rowbase + tt) * 64 + 32 + nn];
    }
    float Av[16];
    bool fast = true;
#pragma unroll
    for (int n = 0; n < 16; ++n) {
        Av[n] = -__expf(A_log[(size_t)d * DSTATE + n]);
        if (fabsf(Av[n] + (float)(n + 1)) > 1e-3f) fast = false;
    }
    __syncthreads();

    float h[16], P[16];
#pragma unroll
    for (int n = 0; n < 16; ++n) { h[n] = 0.f; P[n] = 1.f; }
    const float* dpp = g_delta + rowbase * DINNER + d;
    const float* upp = g_u + rowbase * DINNER + d;

    for (int t0 = 0; t0 < CLEN; t0 += 8) {
        float dl[8], ul[8];
#pragma unroll
        for (int j = 0; j < 8; ++j) {
            dl[j] = dpp[(size_t)(t0 + j) * DINNER];
            ul[j] = upp[(size_t)(t0 + j) * DINNER];
        }
#pragma unroll
        for (int j = 0; j < 8; ++j) {
            int tt = t0 + j;
            float dA[16];
            calc_dA16(fast, dl[j], Av, dA);
            float du = dl[j] * ul[j];
            float4 B0 = *(const float4*)&sB[tt][0];
            float4 B1 = *(const float4*)&sB[tt][4];
            float4 B2 = *(const float4*)&sB[tt][8];
            float4 B3 = *(const float4*)&sB[tt][12];
            h[0]  = dA[0]  * h[0]  + du * B0.x;  h[1]  = dA[1]  * h[1]  + du * B0.y;
            h[2]  = dA[2]  * h[2]  + du * B0.z;  h[3]  = dA[3]  * h[3]  + du * B0.w;
            h[4]  = dA[4]  * h[4]  + du * B1.x;  h[5]  = dA[5]  * h[5]  + du * B1.y;
            h[6]  = dA[6]  * h[6]  + du * B1.z;  h[7]  = dA[7]  * h[7]  + du * B1.w;
            h[8]  = dA[8]  * h[8]  + du * B2.x;  h[9]  = dA[9]  * h[9]  + du * B2.y;
            h[10] = dA[10] * h[10] + du * B2.z;  h[11] = dA[11] * h[11] + du * B2.w;
            h[12] = dA[12] * h[12] + du * B3.x;  h[13] = dA[13] * h[13] + du * B3.y;
            h[14] = dA[14] * h[14] + du * B3.z;  h[15] = dA[15] * h[15] + du * B3.w;
#pragma unroll
            for (int n = 0; n < 16; ++n) P[n] *= dA[n];
        }
    }
    size_t o = (((size_t)b * NCHUNK + k) * DINNER + d) * DSTATE;
#pragma unroll
    for (int g = 0; g < 4; ++g) {
        *(float4*)&g_hpart[o + 4 * g] = make_float4(h[4*g], h[4*g+1], h[4*g+2], h[4*g+3]);
        *(float4*)&g_acum[o + 4 * g]  = make_float4(P[4*g], P[4*g+1], P[4*g+2], P[4*g+3]);
    }
}

// =============================================================================
// Scan pass 2: combine chunk summaries -> incoming state per chunk.
// =============================================================================
__global__ __launch_bounds__(256)
void scan_p2() {
    int idx = blockIdx.x * blockDim.x + threadIdx.x;   // b*16384 + d*16 + n
    int b = idx >> 14, dn = idx & 16383;
    float h = 0.f;
#pragma unroll 4
    for (int k = 0; k < NCHUNK; ++k) {
        size_t o = ((size_t)(b * NCHUNK + k) << 14) + dn;
        g_hin[o] = h;
        h = g_acum[o] * h + g_hpart[o];
    }
}

// =============================================================================
// Scan pass 3: thread-per-channel re-scan from h_in; gated fp16 out (hi only).
// =============================================================================
__global__ __launch_bounds__(128)
void scan_p3(const float* __restrict__ A_log, const float* __restrict__ Dp) {
    __shared__ float sB[CLEN][16];
    __shared__ float sC[CLEN][16];
    int tid = threadIdx.x;
    int k  = blockIdx.x & (NCHUNK - 1);
    int dg = (blockIdx.x >> 5) & 7;
    int b  = blockIdx.x >> 8;
    int d  = dg * 128 + tid;
    size_t rowbase = (size_t)b * SEQ + k * CLEN;

#pragma unroll
    for (int i = 0; i < 8; ++i) {
        int idx = tid + i * 128;
        int tt = idx >> 4, nn = idx & 15;
        sB[tt][nn] = g_xdbl[(rowbase + tt) * 64 + 32 + nn];
        sC[tt][nn] = g_xdbl[(rowbase + tt) * 64 + 48 + nn];
    }
    float Av[16];
    bool fast = true;
#pragma unroll
    for (int n = 0; n < 16; ++n) {
        Av[n] = -__expf(A_log[(size_t)d * DSTATE + n]);
        if (fabsf(Av[n] + (float)(n + 1)) > 1e-3f) fast = false;
    }
    float dpv = Dp[d];
    float h[16];
    size_t o = (((size_t)b * NCHUNK + k) * DINNER + d) * DSTATE;
#pragma unroll
    for (int g = 0; g < 4; ++g) {
        float4 hv = *(const float4*)&g_hin[o + 4 * g];
        h[4*g] = hv.x; h[4*g+1] = hv.y; h[4*g+2] = hv.z; h[4*g+3] = hv.w;
    }
    __syncthreads();

    const float* dpp = g_delta + rowbase * DINNER + d;
    const float* upp = g_u + rowbase * DINNER + d;
    const float* zpp = g_xz + rowbase * (2 * DINNER) + DINNER + d;

    for (int t0 = 0; t0 < CLEN; t0 += 8) {
        float dl[8], ul[8], zl[8];
#pragma unroll
        for (int j = 0; j < 8; ++j) {
            dl[j] = dpp[(size_t)(t0 + j) * DINNER];
            ul[j] = upp[(size_t)(t0 + j) * DINNER];
            zl[j] = zpp[(size_t)(t0 + j) * (2 * DINNER)];
        }
#pragma unroll
        for (int j = 0; j < 8; ++j) {
            int tt = t0 + j;
            float dA[16];
            calc_dA16(fast, dl[j], Av, dA);
            float du = dl[j] * ul[j];
            float4 B0 = *(const float4*)&sB[tt][0];
            float4 B1 = *(const float4*)&sB[tt][4];
            float4 B2 = *(const float4*)&sB[tt][8];
            float4 B3 = *(const float4*)&sB[tt][12];
            h[0]  = dA[0]  * h[0]  + du * B0.x;  h[1]  = dA[1]  * h[1]  + du * B0.y;
            h[2]  = dA[2]  * h[2]  + du * B0.z;  h[3]  = dA[3]  * h[3]  + du * B0.w;
            h[4]  = dA[4]  * h[4]  + du * B1.x;  h[5]  = dA[5]  * h[5]  + du * B1.y;
            h[6]  = dA[6]  * h[6]  + du * B1.z;  h[7]  = dA[7]  * h[7]  + du * B1.w;
            h[8]  = dA[8]  * h[8]  + du * B2.x;  h[9]  = dA[9]  * h[9]  + du * B2.y;
            h[10] = dA[10] * h[10] + du * B2.z;  h[11] = dA[11] * h[11] + du * B2.w;
            h[12] = dA[12] * h[12] + du * B3.x;  h[13] = dA[13] * h[13] + du * B3.y;
            h[14] = dA[14] * h[14] + du * B3.z;  h[15] = dA[15] * h[15] + du * B3.w;
            float4 C0 = *(const float4*)&sC[tt][0];
            float4 C1 = *(const float4*)&sC[tt][4];
            float4 C2 = *(const float4*)&sC[tt][8];
            float4 C3 = *(const float4*)&sC[tt][12];
            float y0 = h[0]*C0.x + h[1]*C0.y + h[2]*C0.z + h[3]*C0.w;
            float y1 = h[4]*C1.x + h[5]*C1.y + h[6]*C1.z + h[7]*C1.w;
            float y2 = h[8]*C2.x + h[9]*C2.y + h[10]*C2.z + h[11]*C2.w;
            float y3 = h[12]*C3.x + h[13]*C3.y + h[14]*C3.z + h[15]*C3.w;
            float y = (y0 + y1) + (y2 + y3);
            float z = zl[j];
            float sig = 1.f / (1.f + __expf(-z));
            float outv = (y + ul[j] * dpv) * (z * sig);
            g_yh[(rowbase + tt) * DINNER + d] = __float2half_rn(outv);
        }
    }
}

// =============================================================================
extern "C" void kernel_launch(void* const* d_in, const int* in_sizes, int n_in,
                              void* d_out, int out_size) {
    const float* x      = (const float*)d_in[0];
    const float* W_in   = (const float*)d_in[1];
    const float* W_conv = (const float*)d_in[2];
    const float* b_conv = (const float*)d_in[3];
    const float* W_x    = (const float*)d_in[4];
    const float* W_dt   = (const float*)d_in[5];
    const float* b_dt   = (const float*)d_in[6];
    const float* A_log  = (const float*)d_in[7];
    const float* Dp     = (const float*)d_in[8];
    const float* W_out  = (const float*)d_in[9];
    float* out = (float*)d_out;

    float* xz_p;
    __half *xh, *wih, *yh, *woh;
    cudaGetSymbolAddress((void**)&xz_p, g_xz);
    cudaGetSymbolAddress((void**)&xh,  g_xh);
    cudaGetSymbolAddress((void**)&wih, g_wih);
    cudaGetSymbolAddress((void**)&yh,  g_yh);
    cudaGetSymbolAddress((void**)&woh, g_woh);

    static int smem_set = 0;
    if (!smem_set) {
        cudaFuncSetAttribute(gemm1t_mma, cudaFuncAttributeMaxDynamicSharedMemorySize,
                             GEMM_SMEM);
        smem_set = 1;
    }

    // 0-2) operand prep (gemm1 stays at launch index 3 for ncu)
    cast16_kernel<<<(NROWS * DMODEL / 4 + 255) / 256, 256>>>(x, xh, NROWS * DMODEL / 4);
    cast16_kernel<<<(2 * DINNER * DMODEL / 4 + 255) / 256, 256>>>(W_in, wih,
                                                                  2 * DINNER * DMODEL / 4);
    cast16_kernel<<<(DMODEL * DINNER / 4 + 255) / 256, 256>>>(W_out, woh,
                                                              DMODEL * DINNER / 4);
    // 3) xz = x @ W_in^T
    gemm1t_mma<<<dim3(2 * DINNER / 128, NROWS / 128), 128, GEMM_SMEM>>>(
        xh, wih, xz_p, NROWS, 2 * DINNER, DMODEL);
    // 4) u = silu(conv(u_pre))
    conv_silu_kernel<<<((NROWS / 4) * DINNER) / 256, 256>>>(W_conv, b_conv);
    // 5) x_dbl = u @ W_x^T
    xdbl_kernel<<<NROWS / 32, 256>>>(W_x);
    // 6) delta = softplus(dt @ W_dt^T + b_dt)
    delta_kernel<<<dim3(DINNER / 256, NROWS / 32), 256>>>(W_dt, b_dt);
    // 7-9) chunked parallel scan, thread-per-channel
    scan_p1<<<BSZ * 8 * NCHUNK, 128>>>(A_log);
    scan_p2<<<BSZ * DINNER * DSTATE / 256, 256>>>();
    scan_p3<<<BSZ * 8 * NCHUNK, 128>>>(A_log, Dp);
    // 10) out = y @ W_out^T
    gemm1t_mma<<<dim3(DMODEL / 128, NROWS / 128), 128, GEMM_SMEM>>>(
        yh, woh, out, NROWS, DMODEL, DINNER);
}

// round 16
// speedup vs baseline: 1.6573x; 1.0204x over previous
#include <cuda_runtime.h>
#include <cuda_fp16.h>
#include <cstdint>

#define BSZ    4
#define SEQ    2048
#define DMODEL 512
#define DINNER 1024
#define DSTATE 16
#define DTRANK 32
#define NROWS  (BSZ*SEQ)   // 8192 flattened (b,t) rows
#define NCHUNK 32          // time chunks for parallel scan
#define CLEN   64          // steps per chunk

// ---------------- scratch (static device allocations; no cudaMalloc allowed) ----
__device__ float g_xz[(size_t)NROWS * 2 * DINNER];   // in-proj output [8192, 2048]
__device__ float g_u[(size_t)NROWS * DINNER];        // conv+silu activations
__device__ float g_xdbl[(size_t)NROWS * 64];         // [dt(32) | B(16) | C(16)]
__device__ float g_delta[(size_t)NROWS * DINNER];    // softplus(dt@W_dt^T + b)

// chunked-scan intermediates
__device__ float g_hpart[(size_t)BSZ * NCHUNK * DINNER * DSTATE];
__device__ float g_acum [(size_t)BSZ * NCHUNK * DINNER * DSTATE];
__device__ float g_hin  [(size_t)BSZ * NCHUNK * DINNER * DSTATE];

// fp16 operands (1-term: activations and weights both rounded to fp16)
__device__ __half g_xh[(size_t)NROWS * DMODEL];
__device__ __half g_wih[(size_t)2 * DINNER * DMODEL];
__device__ __half g_yh[(size_t)NROWS * DINNER];
__device__ __half g_woh[(size_t)DMODEL * DINNER];

// ============================ PTX helpers (sm_100 BASE target only) ==========
__device__ __forceinline__ uint32_t smem_u32(const void* p) {
    uint32_t a;
    asm("{ .reg .u64 t; cvta.to.shared.u64 t, %1; cvt.u32.u64 %0, t; }" : "=r"(a) : "l"(p));
    return a;
}
#define CPA16(s, g) \
    asm volatile("cp.async.cg.shared.global [%0], [%1], 16;" :: "r"(s), "l"(g))
#define CPA_COMMIT() asm volatile("cp.async.commit_group;" ::: "memory")
#define CPA_WAIT(n)  asm volatile("cp.async.wait_group %0;" :: "n"(n) : "memory")
#define LDSM4(r0, r1, r2, r3, a) \
    asm volatile("ldmatrix.sync.aligned.m8n8.x4.shared.b16 {%0,%1,%2,%3}, [%4];" \
                 : "=r"(r0), "=r"(r1), "=r"(r2), "=r"(r3) : "r"(a))
// NOT volatile: register-only op, lets ptxas interleave independent MMAs.
#define MMA16816(d, a, b0, b1) \
    asm("mma.sync.aligned.m16n8k16.row.col.f32.f16.f16.f32 " \
        "{%0,%1,%2,%3}, {%4,%5,%6,%7}, {%8,%9}, {%0,%1,%2,%3};" \
        : "+f"((d)[0]), "+f"((d)[1]), "+f"((d)[2]), "+f"((d)[3]) \
        : "r"((a)[0]), "r"((a)[1]), "r"((a)[2]), "r"((a)[3]), \
          "r"(b0), "r"(b1))

// =============================================================================
// 1-term fp16 GEMM via mma.sync: C[M,N] = fp16(A) @ fp16(B)^T  (fp32 accum)
// CTA 128x128, BK=32, 256 threads (8 warps 2x4, warp tile 64x32 — best measured
// per-MMA efficiency). 2-stage cp.async, 80B smem row stride.
// ~110 regs -> 2 CTAs / 16 warps per SM. Requires M%128==0, N%128==0, K%32==0.
// =============================================================================
#define MAT_B   10240          // 128 rows * 80 B
#define STAGE_B (2*MAT_B)      // Ah, Bh
#define GEMM_SMEM (2*STAGE_B)  // 40,960 B

__global__ __launch_bounds__(256, 1)
void gemm1t_mma(const __half* __restrict__ Ah, const __half* __restrict__ Bh,
                float* __restrict__ C, int M, int N, int K) {
    extern __shared__ char smem[];
    const uint32_t sb = smem_u32(smem);
    const int tid = threadIdx.x, wid = tid >> 5, lid = tid & 31;
    const int wm = wid >> 2, wn = wid & 3;          // 2 x 4 warp grid, 64x32 tiles
    const int n0 = blockIdx.x * 128, m0 = blockIdx.y * 128;
    const int NC = K >> 5;                          // K / 32 chunks

#define ISSUE_STAGE(c) do {                                                    \
    int _k0 = (c) << 5;                                                        \
    uint32_t _sb = sb + (((c) & 1) ? STAGE_B : 0);                             \
    _Pragma("unroll")                                                          \
    for (int i = 0; i < 4; ++i) {                                              \
        int idx = tid + (i << 8);                                              \
        int mat = idx >> 9;                                                    \
        int rc  = idx & 511;                                                   \
        int r   = rc >> 2, cc = rc & 3;                                        \
        const __half* src = (mat == 0 ? Ah : Bh);                              \
        int rowbase = (mat == 0) ? m0 : n0;                                    \
        const __half* g = src + (size_t)(rowbase + r) * K + _k0 + cc * 8;      \
        uint32_t s = _sb + mat * MAT_B + r * 80 + cc * 16;                     \
        CPA16(s, g);                                                           \
    }                                                                          \
    CPA_COMMIT();                                                              \
} while (0)

    float acc[4][4][4];
#pragma unroll
    for (int a = 0; a < 4; ++a)
#pragma unroll
        for (int b = 0; b < 4; ++b)
#pragma unroll
            for (int e = 0; e < 4; ++e) acc[a][b][e] = 0.f;

    const int quad = lid >> 3, lr = lid & 7;
    const int rq = (quad & 1) * 8 + lr;             // row-within-16 for ldmatrix lane
    const int kq = (quad >> 1) * 8;                 // k-offset-within-16 for lane

    ISSUE_STAGE(0);

    for (int c = 0; c < NC; ++c) {
        if (c + 1 < NC) {
            ISSUE_STAGE(c + 1);
            CPA_WAIT(1);
        } else {
            CPA_WAIT(0);
        }
        __syncthreads();
        uint32_t cb = sb + ((c & 1) ? STAGE_B : 0);
        uint32_t ab_h = cb, bb_h = cb + MAT_B;
#pragma unroll
        for (int ks = 0; ks < 2; ++ks) {
            uint32_t ah[4][4], bh[2][4];
            int kk = ks * 16 + kq;
#pragma unroll
            for (int mt = 0; mt < 4; ++mt) {
                uint32_t off = (uint32_t)((wm * 64 + mt * 16 + rq) * 80 + kk * 2);
                LDSM4(ah[mt][0], ah[mt][1], ah[mt][2], ah[mt][3], ab_h + off);
            }
#pragma unroll
            for (int nt = 0; nt < 2; ++nt) {
                uint32_t off = (uint32_t)((wn * 32 + nt * 16 + rq) * 80 + kk * 2);
                LDSM4(bh[nt][0], bh[nt][1], bh[nt][2], bh[nt][3], bb_h + off);
            }
#pragma unroll
            for (int mt = 0; mt < 4; ++mt)
#pragma unroll
                for (int j = 0; j < 4; ++j) {
                    int nt = j >> 1, sel = j & 1;
                    MMA16816(acc[mt][j], ah[mt], bh[nt][sel], bh[nt][sel + 2]);
                }
        }
        __syncthreads();
    }

    // epilogue
    const int gr = lid >> 2, gc = (lid & 3) * 2;
#pragma unroll
    for (int mt = 0; mt < 4; ++mt) {
        int row = m0 + wm * 64 + mt * 16 + gr;
#pragma unroll
        for (int j = 0; j < 4; ++j) {
            int col = n0 + wn * 32 + j * 8 + gc;
            *(float2*)(C + (size_t)row * N + col) =
                make_float2(acc[mt][j][0], acc[mt][j][1]);
            *(float2*)(C + (size_t)(row + 8) * N + col) =
                make_float2(acc[mt][j][2], acc[mt][j][3]);
        }
    }
#undef ISSUE_STAGE
}

// fp32 -> fp16 cast
__global__ void cast16_kernel(const float* __restrict__ s, __half* __restrict__ hi,
                              int n4) {
    int i = blockIdx.x * blockDim.x + threadIdx.x;
    if (i >= n4) return;
    float4 v = ((const float4*)s)[i];
    __half2* hp = (__half2*)hi;
    hp[2 * i + 0] = __halves2half2(__float2half_rn(v.x), __float2half_rn(v.y));
    hp[2 * i + 1] = __halves2half2(__float2half_rn(v.z), __float2half_rn(v.w));
}

// =============================================================================
// Depthwise causal conv (width 4) + SiLU — 4 outputs per thread (sliding window)
// =============================================================================
__global__ void conv_silu_kernel(const float* __restrict__ W_conv,
                                 const float* __restrict__ b_conv) {
    int idx = blockIdx.x * blockDim.x + threadIdx.x;
    if (idx >= (NROWS / 4) * DINNER) return;
    int d  = idx & (DINNER - 1);
    int rg = idx >> 10;                 // row-group (4 rows each)
    int row0 = rg << 2;
    int t0 = row0 & (SEQ - 1);
    const float* base = g_xz + (size_t)row0 * (2 * DINNER) + d;
    float4 w = *(const float4*)(W_conv + d * 4);
    float bias = b_conv[d];
    float xv[7];
#pragma unroll
    for (int j = 0; j < 7; ++j) {
        int t = t0 - 3 + j;
        xv[j] = (t >= 0) ? base[(j - 3) * (2 * DINNER)] : 0.f;
    }
    float* up = g_u + (size_t)row0 * DINNER + d;
#pragma unroll
    for (int i = 0; i < 4; ++i) {
        float acc = bias + xv[i] * w.x + xv[i + 1] * w.y + xv[i + 2] * w.z
                  + xv[i + 3] * w.w;
        float sig = 1.f / (1.f + __expf(-acc));
        up[i * DINNER] = acc * sig;
    }
}

// =============================================================================
// x_dbl[8192,64] = u @ W_x^T
// =============================================================================
__global__ __launch_bounds__(256)
void xdbl_kernel(const float* __restrict__ W_x) {
    __shared__ float Us[32][33];
    __shared__ float Ws[64][33];
    int tid = threadIdx.x;
    int m0  = blockIdx.x * 32;
    int col = tid & 63;
    int rg  = tid >> 6;
    float acc[8] = {};
    for (int k0 = 0; k0 < DINNER; k0 += 32) {
        __syncthreads();
#pragma unroll
        for (int i = 0; i < 4; ++i) {
            int idx = tid + i * 256;
            int r = idx >> 5, k = idx & 31;
            Us[r][k] = g_u[(size_t)(m0 + r) * DINNER + k0 + k];
        }
#pragma unroll
        for (int i = 0; i < 8; ++i) {
            int idx = tid + i * 256;
            int n = idx >> 5, k = idx & 31;
            Ws[n][k] = W_x[(size_t)n * DINNER + k0 + k];
        }
        __syncthreads();
#pragma unroll
        for (int k = 0; k < 32; ++k) {
            float w = Ws[col][k];
#pragma unroll
            for (int rr = 0; rr < 8; ++rr)
                acc[rr] += Us[rg * 8 + rr][k] * w;
        }
    }
#pragma unroll
    for (int rr = 0; rr < 8; ++rr)
        g_xdbl[(size_t)(m0 + rg * 8 + rr) * 64 + col] = acc[rr];
}

// =============================================================================
// delta = softplus(dt @ W_dt^T + b_dt)  — fast softplus via __logf
// =============================================================================
__global__ __launch_bounds__(256)
void delta_kernel(const float* __restrict__ W_dt, const float* __restrict__ b_dt) {
    __shared__ float sdt[32][33];
    __shared__ float sw[256][33];
    int tid = threadIdx.x;
    int m0 = blockIdx.y * 32;
    int n0 = blockIdx.x * 256;
#pragma unroll
    for (int i = 0; i < 4; ++i) {
        int idx = tid + i * 256;
        int r = idx >> 5, k = idx & 31;
        sdt[r][k] = g_xdbl[(size_t)(m0 + r) * 64 + k];
    }
#pragma unroll
    for (int i = 0; i < 32; ++i) {
        int idx = tid + i * 256;
        int n = idx >> 5, k = idx & 31;
        sw[n][k] = W_dt[(size_t)(n0 + n) * DTRANK + k];
    }
    __syncthreads();
    int m  = tid & 63;
    int rg = tid >> 6;
    float acc[8][4];
#pragma unroll
    for (int rr = 0; rr < 8; ++rr)
#pragma unroll
        for (int j = 0; j < 4; ++j) acc[rr][j] = b_dt[n0 + m + 64 * j];
#pragma unroll
    for (int k = 0; k < 32; ++k) {
        float w[4];
#pragma unroll
        for (int j = 0; j < 4; ++j) w[j] = sw[m + 64 * j][k];
#pragma unroll
        for (int rr = 0; rr < 8; ++rr) {
            float dv = sdt[rg * 8 + rr][k];
#pragma unroll
            for (int j = 0; j < 4; ++j) acc[rr][j] += dv * w[j];
        }
    }
#pragma unroll
    for (int rr = 0; rr < 8; ++rr) {
        int row = m0 + rg * 8 + rr;
#pragma unroll
        for (int j = 0; j < 4; ++j) {
            float s  = acc[rr][j];
            float sp = (s > 20.f) ? s : __logf(1.f + __expf(s));
            g_delta[(size_t)row * DINNER + n0 + m + 64 * j] = sp;
        }
    }
}

// ============== thread-per-channel scan: dA helper ===========================
__device__ __forceinline__ void calc_dA16(bool fast, float delta,
                                          const float* Av, float* dA) {
    if (fast) {
        float r  = __expf(-delta);
        float r2 = r * r, r3 = r2 * r, r4 = r2 * r2;
        dA[0] = r;        dA[1] = r2;       dA[2] = r3;       dA[3] = r4;
        dA[4] = r4 * r;   dA[5] = r4 * r2;  dA[6] = r4 * r3;  dA[7] = r4 * r4;
        float r8 = dA[7];
        dA[8]  = r8 * r;      dA[9]  = r8 * r2;     dA[10] = r8 * r3;
        dA[11] = r8 * r4;     dA[12] = r8 * dA[4];  dA[13] = r8 * dA[5];
        dA[14] = r8 * dA[6];  dA[15] = r8 * r8;
    } else {
#pragma unroll
        for (int n = 0; n < 16; ++n) dA[n] = __expf(delta * Av[n]);
    }
}

// =============================================================================
// Scan pass 1: thread-per-channel (16 states).
// =============================================================================
__global__ __launch_bounds__(128)
void scan_p1(const float* __restrict__ A_log) {
    __shared__ float sB[CLEN][16];
    int tid = threadIdx.x;
    int k  = blockIdx.x & (NCHUNK - 1);
    int dg = (blockIdx.x >> 5) & 7;
    int b  = blockIdx.x >> 8;
    int d  = dg * 128 + tid;
    size_t rowbase = (size_t)b * SEQ + k * CLEN;

#pragma unroll
    for (int i = 0; i < 8; ++i) {
        int idx = tid + i * 128;
        int tt = idx >> 4, nn = idx & 15;
        sB[tt][nn] = g_xdbl[(rowbase + tt) * 64 + 32 + nn];
    }
    float Av[16];
    bool fast = true;
#pragma unroll
    for (int n = 0; n < 16; ++n) {
        Av[n] = -__expf(A_log[(size_t)d * DSTATE + n]);
        if (fabsf(Av[n] + (float)(n + 1)) > 1e-3f) fast = false;
    }
    __syncthreads();

    float h[16], P[16];
#pragma unroll
    for (int n = 0; n < 16; ++n) { h[n] = 0.f; P[n] = 1.f; }
    const float* dpp = g_delta + rowbase * DINNER + d;
    const float* upp = g_u + rowbase * DINNER + d;

    for (int t0 = 0; t0 < CLEN; t0 += 8) {
        float dl[8], ul[8];
#pragma unroll
        for (int j = 0; j < 8; ++j) {
            dl[j] = dpp[(size_t)(t0 + j) * DINNER];
            ul[j] = upp[(size_t)(t0 + j) * DINNER];
        }
#pragma unroll
        for (int j = 0; j < 8; ++j) {
            int tt = t0 + j;
            float dA[16];
            calc_dA16(fast, dl[j], Av, dA);
            float du = dl[j] * ul[j];
            float4 B0 = *(const float4*)&sB[tt][0];
            float4 B1 = *(const float4*)&sB[tt][4];
            float4 B2 = *(const float4*)&sB[tt][8];
            float4 B3 = *(const float4*)&sB[tt][12];
            h[0]  = dA[0]  * h[0]  + du * B0.x;  h[1]  = dA[1]  * h[1]  + du * B0.y;
            h[2]  = dA[2]  * h[2]  + du * B0.z;  h[3]  = dA[3]  * h[3]  + du * B0.w;
            h[4]  = dA[4]  * h[4]  + du * B1.x;  h[5]  = dA[5]  * h[5]  + du * B1.y;
            h[6]  = dA[6]  * h[6]  + du * B1.z;  h[7]  = dA[7]  * h[7]  + du * B1.w;
            h[8]  = dA[8]  * h[8]  + du * B2.x;  h[9]  = dA[9]  * h[9]  + du * B2.y;
            h[10] = dA[10] * h[10] + du * B2.z;  h[11] = dA[11] * h[11] + du * B2.w;
            h[12] = dA[12] * h[12] + du * B3.x;  h[13] = dA[13] * h[13] + du * B3.y;
            h[14] = dA[14] * h[14] + du * B3.z;  h[15] = dA[15] * h[15] + du * B3.w;
#pragma unroll
            for (int n = 0; n < 16; ++n) P[n] *= dA[n];
        }
    }
    size_t o = (((size_t)b * NCHUNK + k) * DINNER + d) * DSTATE;
#pragma unroll
    for (int g = 0; g < 4; ++g) {
        *(float4*)&g_hpart[o + 4 * g] = make_float4(h[4*g], h[4*g+1], h[4*g+2], h[4*g+3]);
        *(float4*)&g_acum[o + 4 * g]  = make_float4(P[4*g], P[4*g+1], P[4*g+2], P[4*g+3]);
    }
}

// =============================================================================
// Scan pass 2: combine chunk summaries -> incoming state per chunk.
// =============================================================================
__global__ __launch_bounds__(256)
void scan_p2() {
    int idx = blockIdx.x * blockDim.x + threadIdx.x;   // b*16384 + d*16 + n
    int b = idx >> 14, dn = idx & 16383;
    float h = 0.f;
#pragma unroll 4
    for (int k = 0; k < NCHUNK; ++k) {
        size_t o = ((size_t)(b * NCHUNK + k) << 14) + dn;
        g_hin[o] = h;
        h = g_acum[o] * h + g_hpart[o];
    }
}

// =============================================================================
// Scan pass 3: thread-per-channel re-scan from h_in; gated fp16 out.
// =============================================================================
__global__ __launch_bounds__(128)
void scan_p3(const float* __restrict__ A_log, const float* __restrict__ Dp) {
    __shared__ float sB[CLEN][16];
    __shared__ float sC[CLEN][16];
    int tid = threadIdx.x;
    int k  = blockIdx.x & (NCHUNK - 1);
    int dg = (blockIdx.x >> 5) & 7;
    int b  = blockIdx.x >> 8;
    int d  = dg * 128 + tid;
    size_t rowbase = (size_t)b * SEQ + k * CLEN;

#pragma unroll
    for (int i = 0; i < 8; ++i) {
        int idx = tid + i * 128;
        int tt = idx >> 4, nn = idx & 15;
        sB[tt][nn] = g_xdbl[(rowbase + tt) * 64 + 32 + nn];
        sC[tt][nn] = g_xdbl[(rowbase + tt) * 64 + 48 + nn];
    }
    float Av[16];
    bool fast = true;
#pragma unroll
    for (int n = 0; n < 16; ++n) {
        Av[n] = -__expf(A_log[(size_t)d * DSTATE + n]);
        if (fabsf(Av[n] + (float)(n + 1)) > 1e-3f) fast = false;
    }
    float dpv = Dp[d];
    float h[16];
    size_t o = (((size_t)b * NCHUNK + k) * DINNER + d) * DSTATE;
#pragma unroll
    for (int g = 0; g < 4; ++g) {
        float4 hv = *(const float4*)&g_hin[o + 4 * g];
        h[4*g] = hv.x; h[4*g+1] = hv.y; h[4*g+2] = hv.z; h[4*g+3] = hv.w;
    }
    __syncthreads();

    const float* dpp = g_delta + rowbase * DINNER + d;
    const float* upp = g_u + rowbase * DINNER + d;
    const float* zpp = g_xz + rowbase * (2 * DINNER) + DINNER + d;

    for (int t0 = 0; t0 < CLEN; t0 += 8) {
        float dl[8], ul[8], zl[8];
#pragma unroll
        for (int j = 0; j < 8; ++j) {
            dl[j] = dpp[(size_t)(t0 + j) * DINNER];
            ul[j] = upp[(size_t)(t0 + j) * DINNER];
            zl[j] = zpp[(size_t)(t0 + j) * (2 * DINNER)];
        }
#pragma unroll
        for (int j = 0; j < 8; ++j) {
            int tt = t0 + j;
            float dA[16];
            calc_dA16(fast, dl[j], Av, dA);
            float du = dl[j] * ul[j];
            float4 B0 = *(const float4*)&sB[tt][0];
            float4 B1 = *(const float4*)&sB[tt][4];
            float4 B2 = *(const float4*)&sB[tt][8];
            float4 B3 = *(const float4*)&sB[tt][12];
            h[0]  = dA[0]  * h[0]  + du * B0.x;  h[1]  = dA[1]  * h[1]  + du * B0.y;
            h[2]  = dA[2]  * h[2]  + du * B0.z;  h[3]  = dA[3]  * h[3]  + du * B0.w;
            h[4]  = dA[4]  * h[4]  + du * B1.x;  h[5]  = dA[5]  * h[5]  + du * B1.y;
            h[6]  = dA[6]  * h[6]  + du * B1.z;  h[7]  = dA[7]  * h[7]  + du * B1.w;
            h[8]  = dA[8]  * h[8]  + du * B2.x;  h[9]  = dA[9]  * h[9]  + du * B2.y;
            h[10] = dA[10] * h[10] + du * B2.z;  h[11] = dA[11] * h[11] + du * B2.w;
            h[12] = dA[12] * h[12] + du * B3.x;  h[13] = dA[13] * h[13] + du * B3.y;
            h[14] = dA[14] * h[14] + du * B3.z;  h[15] = dA[15] * h[15] + du * B3.w;
            float4 C0 = *(const float4*)&sC[tt][0];
            float4 C1 = *(const float4*)&sC[tt][4];
            float4 C2 = *(const float4*)&sC[tt][8];
            float4 C3 = *(const float4*)&sC[tt][12];
            float y0 = h[0]*C0.x + h[1]*C0.y + h[2]*C0.z + h[3]*C0.w;
            float y1 = h[4]*C1.x + h[5]*C1.y + h[6]*C1.z + h[7]*C1.w;
            float y2 = h[8]*C2.x + h[9]*C2.y + h[10]*C2.z + h[11]*C2.w;
            float y3 = h[12]*C3.x + h[13]*C3.y + h[14]*C3.z + h[15]*C3.w;
            float y = (y0 + y1) + (y2 + y3);
            float z = zl[j];
            float sig = 1.f / (1.f + __expf(-z));
            float outv = (y + ul[j] * dpv) * (z * sig);
            g_yh[(rowbase + tt) * DINNER + d] = __float2half_rn(outv);
        }
    }
}

// =============================================================================
extern "C" void kernel_launch(void* const* d_in, const int* in_sizes, int n_in,
                              void* d_out, int out_size) {
    const float* x      = (const float*)d_in[0];
    const float* W_in   = (const float*)d_in[1];
    const float* W_conv = (const float*)d_in[2];
    const float* b_conv = (const float*)d_in[3];
    const float* W_x    = (const float*)d_in[4];
    const float* W_dt   = (const float*)d_in[5];
    const float* b_dt   = (const float*)d_in[6];
    const float* A_log  = (const float*)d_in[7];
    const float* Dp     = (const float*)d_in[8];
    const float* W_out  = (const float*)d_in[9];
    float* out = (float*)d_out;

    float* xz_p;
    __half *xh, *wih, *yh, *woh;
    cudaGetSymbolAddress((void**)&xz_p, g_xz);
    cudaGetSymbolAddress((void**)&xh,  g_xh);
    cudaGetSymbolAddress((void**)&wih, g_wih);
    cudaGetSymbolAddress((void**)&yh,  g_yh);
    cudaGetSymbolAddress((void**)&woh, g_woh);

    static int smem_set = 0;
    if (!smem_set) {
        cudaFuncSetAttribute(gemm1t_mma, cudaFuncAttributeMaxDynamicSharedMemorySize,
                             GEMM_SMEM);
        smem_set = 1;
    }

    // 0-2) operand prep (gemm1 stays at launch index 3 for ncu)
    cast16_kernel<<<(NROWS * DMODEL / 4 + 255) / 256, 256>>>(x, xh, NROWS * DMODEL / 4);
    cast16_kernel<<<(2 * DINNER * DMODEL / 4 + 255) / 256, 256>>>(W_in, wih,
                                                                  2 * DINNER * DMODEL / 4);
    cast16_kernel<<<(DMODEL * DINNER / 4 + 255) / 256, 256>>>(W_out, woh,
                                                              DMODEL * DINNER / 4);
    // 3) xz = x @ W_in^T
    gemm1t_mma<<<dim3(2 * DINNER / 128, NROWS / 128), 256, GEMM_SMEM>>>(
        xh, wih, xz_p, NROWS, 2 * DINNER, DMODEL);
    // 4) u = silu(conv(u_pre))
    conv_silu_kernel<<<((NROWS / 4) * DINNER) / 256, 256>>>(W_conv, b_conv);
    // 5) x_dbl = u @ W_x^T
    xdbl_kernel<<<NROWS / 32, 256>>>(W_x);
    // 6) delta = softplus(dt @ W_dt^T + b_dt)
    delta_kernel<<<dim3(DINNER / 256, NROWS / 32), 256>>>(W_dt, b_dt);
    // 7-9) chunked parallel scan, thread-per-channel
    scan_p1<<<BSZ * 8 * NCHUNK, 128>>>(A_log);
    scan_p2<<<BSZ * DINNER * DSTATE / 256, 256>>>();
    scan_p3<<<BSZ * 8 * NCHUNK, 128>>>(A_log, Dp);
    // 10) out = y @ W_out^T
    gemm1t_mma<<<dim3(DMODEL / 128, NROWS / 128), 256, GEMM_SMEM>>>(
        yh, woh, out, NROWS, DMODEL, DINNER);
}